// round 2
// baseline (speedup 1.0000x reference)
#include <cuda_runtime.h>
#include <cuda_bf16.h>

#define SB 2048
#define BB 32
#define DD 512
#define HH 512
#define G4 2048
#define MTOT (SB*BB)

// ---- device scratch (static __device__ globals; no allocations) ----
__device__ float    g_gx[(size_t)MTOT * G4];    // input projections for current layer
__device__ unsigned g_hseq[(size_t)MTOT * HH];  // layer-0 h sequence, packed (hi16|lo16)
__device__ unsigned g_h1[BB * HH];              // layer-1 current h, packed
__device__ unsigned g_bar;                      // grid barrier counter

static __device__ __forceinline__ void split_bf16(float v, unsigned short& hi, unsigned short& lo) {
    __nv_bfloat16 h = __float2bfloat16_rn(v);
    float r = v - __bfloat162float(h);
    hi = __bfloat16_as_ushort(h);
    lo = __bfloat16_as_ushort(__float2bfloat16_rn(r));
}

static __device__ __forceinline__ void mma16816(float* d, const unsigned* a, const unsigned* b) {
    asm volatile(
        "mma.sync.aligned.m16n8k16.row.col.f32.bf16.bf16.f32 "
        "{%0,%1,%2,%3}, {%4,%5,%6,%7}, {%8,%9}, {%0,%1,%2,%3};\n"
        : "+f"(d[0]), "+f"(d[1]), "+f"(d[2]), "+f"(d[3])
        : "r"(a[0]), "r"(a[1]), "r"(a[2]), "r"(a[3]), "r"(b[0]), "r"(b[1]));
}

static __device__ __forceinline__ float sigf(float x) { return 1.0f / (1.0f + expf(-x)); }

// ============================================================================
// gx[m][n] = A[m][:].W[n][:] + bias[n];  m = s*32+b.  SRCX=1: A=X fp32, else A=g_hseq packed.
// grid (32 nblk, 512 mblk), 256 threads. CTA tile 128x64, K-chunk 32.
// ============================================================================
template <int SRCX>
__global__ void __launch_bounds__(256) gx_gemm(const float* __restrict__ Xf,
                                               const float* __restrict__ W,
                                               const float* __restrict__ bia,
                                               const float* __restrict__ bib) {
    __shared__ __align__(16) unsigned short sAhi[128][36], sAlo[128][36];
    __shared__ __align__(16) unsigned short sBhi[64][36],  sBlo[64][36];
    __shared__ float sBias[64];

    const int tid = threadIdx.x;
    const int n0 = blockIdx.x * 64, m0 = blockIdx.y * 128;
    if (tid < 64) sBias[tid] = bia[n0 + tid] + bib[n0 + tid];

    const int w = tid >> 5, lane = tid & 31;
    const int wm = w >> 1, wn = w & 1;

    float C[2][4][4];
#pragma unroll
    for (int i = 0; i < 2; i++)
#pragma unroll
        for (int j = 0; j < 4; j++)
#pragma unroll
            for (int k = 0; k < 4; k++) C[i][j][k] = 0.f;

    const int rg = tid >> 3, kq = (tid & 7) * 4;

    for (int kc = 0; kc < 16; kc++) {
        const int k0 = kc * 32;
#pragma unroll
        for (int rr = 0; rr < 4; rr++) {
            const int r = rg + rr * 32, m = m0 + r;
            if (SRCX) {
                const int b = m & 31, s = m >> 5;
                const float4 f = *reinterpret_cast<const float4*>(Xf + ((size_t)(b * SB + s)) * DD + k0 + kq);
                const float v[4] = {f.x, f.y, f.z, f.w};
#pragma unroll
                for (int j = 0; j < 4; j++) {
                    unsigned short hi, lo; split_bf16(v[j], hi, lo);
                    sAhi[r][kq + j] = hi; sAlo[r][kq + j] = lo;
                }
            } else {
                const uint4 u = *reinterpret_cast<const uint4*>(g_hseq + (size_t)m * HH + k0 + kq);
                const unsigned uu[4] = {u.x, u.y, u.z, u.w};
#pragma unroll
                for (int j = 0; j < 4; j++) {
                    sAhi[r][kq + j] = (unsigned short)(uu[j] >> 16);
                    sAlo[r][kq + j] = (unsigned short)(uu[j] & 0xffffu);
                }
            }
        }
#pragma unroll
        for (int rr = 0; rr < 2; rr++) {
            const int r = rg + rr * 32;
            const float4 f = *reinterpret_cast<const float4*>(W + (size_t)(n0 + r) * DD + k0 + kq);
            const float v[4] = {f.x, f.y, f.z, f.w};
#pragma unroll
            for (int j = 0; j < 4; j++) {
                unsigned short hi, lo; split_bf16(v[j], hi, lo);
                sBhi[r][kq + j] = hi; sBlo[r][kq + j] = lo;
            }
        }
        __syncthreads();

#pragma unroll
        for (int ks = 0; ks < 2; ks++) {
            const int kk = ks * 16 + (lane & 3) * 2;
            unsigned Ah[2][4], Al[2][4], Bh[4][2], Bl[4][2];
#pragma unroll
            for (int mt = 0; mt < 2; mt++) {
                const int r = wm * 32 + mt * 16 + (lane >> 2);
                Ah[mt][0] = *(const unsigned*)&sAhi[r][kk];
                Ah[mt][1] = *(const unsigned*)&sAhi[r + 8][kk];
                Ah[mt][2] = *(const unsigned*)&sAhi[r][kk + 8];
                Ah[mt][3] = *(const unsigned*)&sAhi[r + 8][kk + 8];
                Al[mt][0] = *(const unsigned*)&sAlo[r][kk];
                Al[mt][1] = *(const unsigned*)&sAlo[r + 8][kk];
                Al[mt][2] = *(const unsigned*)&sAlo[r][kk + 8];
                Al[mt][3] = *(const unsigned*)&sAlo[r + 8][kk + 8];
            }
#pragma unroll
            for (int nt = 0; nt < 4; nt++) {
                const int n = wn * 32 + nt * 8 + (lane >> 2);
                Bh[nt][0] = *(const unsigned*)&sBhi[n][kk];
                Bh[nt][1] = *(const unsigned*)&sBhi[n][kk + 8];
                Bl[nt][0] = *(const unsigned*)&sBlo[n][kk];
                Bl[nt][1] = *(const unsigned*)&sBlo[n][kk + 8];
            }
#pragma unroll
            for (int mt = 0; mt < 2; mt++)
#pragma unroll
                for (int nt = 0; nt < 4; nt++) {
                    mma16816(C[mt][nt], Ah[mt], Bh[nt]);
                    mma16816(C[mt][nt], Ah[mt], Bl[nt]);
                    mma16816(C[mt][nt], Al[mt], Bh[nt]);
                }
        }
        __syncthreads();
    }

#pragma unroll
    for (int mt = 0; mt < 2; mt++)
#pragma unroll
        for (int nt = 0; nt < 4; nt++) {
            const int r  = m0 + wm * 32 + mt * 16 + (lane >> 2);
            const int cn = wn * 32 + nt * 8 + (lane & 3) * 2;
            const float b0v = sBias[cn], b1v = sBias[cn + 1];
            *reinterpret_cast<float2*>(g_gx + (size_t)r * G4 + n0 + cn) =
                make_float2(C[mt][nt][0] + b0v, C[mt][nt][1] + b1v);
            *reinterpret_cast<float2*>(g_gx + (size_t)(r + 8) * G4 + n0 + cn) =
                make_float2(C[mt][nt][2] + b0v, C[mt][nt][3] + b1v);
        }
}

__global__ void zero_bar() { g_bar = 0; }

// ============================================================================
// Persistent recurrence: 128 CTAs (64 unit-groups x 2 batch-halves), 256 thr.
// Warp = (gate g, K-half kh). Whh slice pre-split into 64 regs of bf16 frags.
// ============================================================================
__global__ void __launch_bounds__(256) lstm_rec(const float* __restrict__ Whh,
                                                int layer, float* __restrict__ dout) {
    __shared__ __align__(16) unsigned short sHhi[16][520], sHlo[16][520];
    __shared__ float sRed[4][16][8], sGate[4][16][8];

    const int tid = threadIdx.x;
    const int ug = blockIdx.x >> 1, u0 = ug * 8;
    const int bg = blockIdx.x & 1,  b0 = bg * 16;
    const int w = tid >> 5, lane = tid & 31;
    const int g = w >> 1, kh = w & 1, kbase = kh * 256;

    // preload register-resident Whh fragments (split hi/lo)
    unsigned Bwhi[16][2], Bwlo[16][2];
    {
        const float* wr = Whh + (size_t)(g * 512 + u0 + (lane >> 2)) * HH + kbase;
#pragma unroll
        for (int ks = 0; ks < 16; ks++) {
            const int k = ks * 16 + (lane & 3) * 2;
            unsigned short h0, l0, h1, l1;
            split_bf16(wr[k], h0, l0);     split_bf16(wr[k + 1], h1, l1);
            Bwhi[ks][0] = (unsigned)h0 | ((unsigned)h1 << 16);
            Bwlo[ks][0] = (unsigned)l0 | ((unsigned)l1 << 16);
            split_bf16(wr[k + 8], h0, l0); split_bf16(wr[k + 9], h1, l1);
            Bwhi[ks][1] = (unsigned)h0 | ((unsigned)h1 << 16);
            Bwlo[ks][1] = (unsigned)l0 | ((unsigned)l1 << 16);
        }
    }

    float cst = 0.f;   // cell state for thread's (batch, unit) pair (tid<128)
    const int bl = tid >> 3, ul = tid & 7;

    for (int t = 0; t < SB; t++) {
        // ---- stage h_{t-1} (packed) into SMEM, unpacking hi/lo ----
        const uint4* src = nullptr;
        if (t > 0)
            src = (layer == 0)
                ? reinterpret_cast<const uint4*>(g_hseq + ((size_t)(t - 1) * BB + b0) * HH)
                : reinterpret_cast<const uint4*>(g_h1 + b0 * HH);
#pragma unroll
        for (int j = 0; j < 8; j++) {
            const int i4 = tid + j * 256;
            uint4 v = src ? src[i4] : make_uint4(0, 0, 0, 0);
            const int idx = i4 * 4, r = idx >> 9, c = idx & 511;
            unsigned* ph = (unsigned*)&sHhi[r][c];
            unsigned* pl = (unsigned*)&sHlo[r][c];
            ph[0] = (v.x >> 16) | (v.y & 0xffff0000u);
            pl[0] = (v.x & 0xffffu) | (v.y << 16);
            ph[1] = (v.z >> 16) | (v.w & 0xffff0000u);
            pl[1] = (v.z & 0xffffu) | (v.w << 16);
        }
        __syncthreads();

        // ---- recurrent MMA: C = h_{t-1} . Whh_slice^T (3-pass split) ----
        float Cr[4] = {0.f, 0.f, 0.f, 0.f};
#pragma unroll
        for (int ks = 0; ks < 16; ks++) {
            const int kk = kbase + ks * 16 + (lane & 3) * 2;
            const int r = lane >> 2;
            unsigned ah[4], al[4];
            ah[0] = *(const unsigned*)&sHhi[r][kk];
            ah[1] = *(const unsigned*)&sHhi[r + 8][kk];
            ah[2] = *(const unsigned*)&sHhi[r][kk + 8];
            ah[3] = *(const unsigned*)&sHhi[r + 8][kk + 8];
            al[0] = *(const unsigned*)&sHlo[r][kk];
            al[1] = *(const unsigned*)&sHlo[r + 8][kk];
            al[2] = *(const unsigned*)&sHlo[r][kk + 8];
            al[3] = *(const unsigned*)&sHlo[r + 8][kk + 8];
            mma16816(Cr, ah, Bwhi[ks]);
            mma16816(Cr, ah, Bwlo[ks]);
            mma16816(Cr, al, Bwhi[ks]);
        }

        // ---- reduce K-halves through SMEM ----
        const int rr = lane >> 2, cc = (lane & 3) * 2;
        if (kh == 1) {
            sRed[g][rr][cc] = Cr[0];     sRed[g][rr][cc + 1] = Cr[1];
            sRed[g][rr + 8][cc] = Cr[2]; sRed[g][rr + 8][cc + 1] = Cr[3];
        }
        __syncthreads();
        if (kh == 0) {
            sGate[g][rr][cc]     = Cr[0] + sRed[g][rr][cc];
            sGate[g][rr][cc + 1] = Cr[1] + sRed[g][rr][cc + 1];
            sGate[g][rr + 8][cc]     = Cr[2] + sRed[g][rr + 8][cc];
            sGate[g][rr + 8][cc + 1] = Cr[3] + sRed[g][rr + 8][cc + 1];
        }
        __syncthreads();

        // ---- LSTM elementwise (128 threads own one (batch,unit) each) ----
        if (tid < 128) {
            const size_t m = (size_t)t * BB + b0 + bl;
            const float* gp = g_gx + m * G4 + u0 + ul;
            const float iv = sGate[0][bl][ul] + gp[0];
            const float fv = sGate[1][bl][ul] + gp[512];
            const float gv = sGate[2][bl][ul] + gp[1024];
            const float ov = sGate[3][bl][ul] + gp[1536];
            cst = sigf(fv) * cst + sigf(iv) * tanhf(gv);
            const float h = sigf(ov) * tanhf(cst);
            unsigned short hh, hl; split_bf16(h, hh, hl);
            const unsigned hp = ((unsigned)hh << 16) | (unsigned)hl;
            if (layer == 0) {
                g_hseq[((size_t)t * BB + b0 + bl) * HH + u0 + ul] = hp;
            } else {
                g_h1[(b0 + bl) * HH + u0 + ul] = hp;
                dout[((size_t)(b0 + bl) * SB + t) * HH + u0 + ul] = h;
            }
            __threadfence();
        }
        __syncthreads();

        // ---- grid barrier (monotonic counter) ----
        if (tid == 0) {
            atomicAdd(&g_bar, 1u);
            const unsigned tgt = 128u * (unsigned)(t + 1);
            while (*(volatile unsigned*)&g_bar < tgt) { }
            __threadfence();
        }
        __syncthreads();
    }
}

extern "C" void kernel_launch(void* const* d_in, const int* in_sizes, int n_in,
                              void* d_out, int out_size) {
    const float* X   = (const float*)d_in[0];
    const float* Wih = (const float*)d_in[1];
    const float* Whh = (const float*)d_in[2];
    const float* bih = (const float*)d_in[3];
    const float* bhh = (const float*)d_in[4];
    float* out = (float*)d_out;

    dim3 gg(32, 512);
    // layer 0
    gx_gemm<1><<<gg, 256>>>(X, Wih, bih, bhh);
    zero_bar<<<1, 1>>>();
    lstm_rec<<<128, 256>>>(Whh, 0, nullptr);
    // layer 1
    gx_gemm<0><<<gg, 256>>>(nullptr, Wih + (size_t)G4 * DD, bih + G4, bhh + G4);
    zero_bar<<<1, 1>>>();
    lstm_rec<<<128, 256>>>(Whh + (size_t)G4 * HH, 1, out);
}

// round 3
// speedup vs baseline: 1.0008x; 1.0008x over previous
#include <cuda_runtime.h>
#include <cuda_bf16.h>

#define SB 2048
#define BB 32
#define DD 512
#define HH 512
#define G4 2048
#define MTOT (SB*BB)

// ---- device scratch (static __device__ globals; no allocations) ----
__device__ float    g_gx[(size_t)MTOT * G4];    // input projections for current layer
__device__ unsigned g_hseq[(size_t)MTOT * HH];  // layer-0 h sequence, packed (hi16|lo16)
__device__ unsigned g_h1[BB * HH];              // layer-1 current h, packed
__device__ unsigned g_bar;                      // grid barrier counter

static __device__ __forceinline__ void split_bf16(float v, unsigned short& hi, unsigned short& lo) {
    __nv_bfloat16 h = __float2bfloat16_rn(v);
    float r = v - __bfloat162float(h);
    hi = __bfloat16_as_ushort(h);
    lo = __bfloat16_as_ushort(__float2bfloat16_rn(r));
}

static __device__ __forceinline__ void mma16816(float* d, const unsigned* a, const unsigned* b) {
    asm volatile(
        "mma.sync.aligned.m16n8k16.row.col.f32.bf16.bf16.f32 "
        "{%0,%1,%2,%3}, {%4,%5,%6,%7}, {%8,%9}, {%0,%1,%2,%3};\n"
        : "+f"(d[0]), "+f"(d[1]), "+f"(d[2]), "+f"(d[3])
        : "r"(a[0]), "r"(a[1]), "r"(a[2]), "r"(a[3]), "r"(b[0]), "r"(b[1]));
}

static __device__ __forceinline__ float sigf(float x) { return 1.0f / (1.0f + expf(-x)); }

// ============================================================================
// gx[m][n] = A[m][:].W[n][:] + bias[n];  m = s*32+b.  SRCX=1: A=X fp32, else A=g_hseq packed.
// ============================================================================
template <int SRCX>
__global__ void __launch_bounds__(256) gx_gemm(const float* __restrict__ Xf,
                                               const float* __restrict__ W,
                                               const float* __restrict__ bia,
                                               const float* __restrict__ bib) {
    __shared__ __align__(16) unsigned short sAhi[128][36], sAlo[128][36];
    __shared__ __align__(16) unsigned short sBhi[64][36],  sBlo[64][36];
    __shared__ float sBias[64];

    const int tid = threadIdx.x;
    const int n0 = blockIdx.x * 64, m0 = blockIdx.y * 128;
    if (tid < 64) sBias[tid] = bia[n0 + tid] + bib[n0 + tid];

    const int w = tid >> 5, lane = tid & 31;
    const int wm = w >> 1, wn = w & 1;

    float C[2][4][4];
#pragma unroll
    for (int i = 0; i < 2; i++)
#pragma unroll
        for (int j = 0; j < 4; j++)
#pragma unroll
            for (int k = 0; k < 4; k++) C[i][j][k] = 0.f;

    const int rg = tid >> 3, kq = (tid & 7) * 4;

    for (int kc = 0; kc < 16; kc++) {
        const int k0 = kc * 32;
#pragma unroll
        for (int rr = 0; rr < 4; rr++) {
            const int r = rg + rr * 32, m = m0 + r;
            if (SRCX) {
                const int b = m & 31, s = m >> 5;
                const float4 f = *reinterpret_cast<const float4*>(Xf + ((size_t)(b * SB + s)) * DD + k0 + kq);
                const float v[4] = {f.x, f.y, f.z, f.w};
#pragma unroll
                for (int j = 0; j < 4; j++) {
                    unsigned short hi, lo; split_bf16(v[j], hi, lo);
                    sAhi[r][kq + j] = hi; sAlo[r][kq + j] = lo;
                }
            } else {
                const uint4 u = *reinterpret_cast<const uint4*>(g_hseq + (size_t)m * HH + k0 + kq);
                const unsigned uu[4] = {u.x, u.y, u.z, u.w};
#pragma unroll
                for (int j = 0; j < 4; j++) {
                    sAhi[r][kq + j] = (unsigned short)(uu[j] >> 16);
                    sAlo[r][kq + j] = (unsigned short)(uu[j] & 0xffffu);
                }
            }
        }
#pragma unroll
        for (int rr = 0; rr < 2; rr++) {
            const int r = rg + rr * 32;
            const float4 f = *reinterpret_cast<const float4*>(W + (size_t)(n0 + r) * DD + k0 + kq);
            const float v[4] = {f.x, f.y, f.z, f.w};
#pragma unroll
            for (int j = 0; j < 4; j++) {
                unsigned short hi, lo; split_bf16(v[j], hi, lo);
                sBhi[r][kq + j] = hi; sBlo[r][kq + j] = lo;
            }
        }
        __syncthreads();

#pragma unroll
        for (int ks = 0; ks < 2; ks++) {
            const int kk = ks * 16 + (lane & 3) * 2;
            unsigned Ah[2][4], Al[2][4], Bh[4][2], Bl[4][2];
#pragma unroll
            for (int mt = 0; mt < 2; mt++) {
                const int r = wm * 32 + mt * 16 + (lane >> 2);
                Ah[mt][0] = *(const unsigned*)&sAhi[r][kk];
                Ah[mt][1] = *(const unsigned*)&sAhi[r + 8][kk];
                Ah[mt][2] = *(const unsigned*)&sAhi[r][kk + 8];
                Ah[mt][3] = *(const unsigned*)&sAhi[r + 8][kk + 8];
                Al[mt][0] = *(const unsigned*)&sAlo[r][kk];
                Al[mt][1] = *(const unsigned*)&sAlo[r + 8][kk];
                Al[mt][2] = *(const unsigned*)&sAlo[r][kk + 8];
                Al[mt][3] = *(const unsigned*)&sAlo[r + 8][kk + 8];
            }
#pragma unroll
            for (int nt = 0; nt < 4; nt++) {
                const int n = wn * 32 + nt * 8 + (lane >> 2);
                Bh[nt][0] = *(const unsigned*)&sBhi[n][kk];
                Bh[nt][1] = *(const unsigned*)&sBhi[n][kk + 8];
                Bl[nt][0] = *(const unsigned*)&sBlo[n][kk];
                Bl[nt][1] = *(const unsigned*)&sBlo[n][kk + 8];
            }
#pragma unroll
            for (int mt = 0; mt < 2; mt++)
#pragma unroll
                for (int nt = 0; nt < 4; nt++) {
                    mma16816(C[mt][nt], Ah[mt], Bh[nt]);
                    mma16816(C[mt][nt], Ah[mt], Bl[nt]);
                    mma16816(C[mt][nt], Al[mt], Bh[nt]);
                }
        }
        __syncthreads();
    }

#pragma unroll
    for (int mt = 0; mt < 2; mt++)
#pragma unroll
        for (int nt = 0; nt < 4; nt++) {
            const int r  = m0 + wm * 32 + mt * 16 + (lane >> 2);
            const int cn = wn * 32 + nt * 8 + (lane & 3) * 2;
            const float b0v = sBias[cn], b1v = sBias[cn + 1];
            *reinterpret_cast<float2*>(g_gx + (size_t)r * G4 + n0 + cn) =
                make_float2(C[mt][nt][0] + b0v, C[mt][nt][1] + b1v);
            *reinterpret_cast<float2*>(g_gx + (size_t)(r + 8) * G4 + n0 + cn) =
                make_float2(C[mt][nt][2] + b0v, C[mt][nt][3] + b1v);
        }
}

__global__ void zero_bar() { g_bar = 0; }

// ============================================================================
// Persistent recurrence: 128 CTAs (64 unit-groups x 2 batch-halves), 256 thr.
// Warp = (gate g, K-half kh). Whh slice pre-split into 64 regs of bf16 frags.
// h kept PACKED (hi16|lo16) in SMEM; PRMT split at fragment build.
// Barrier: release-red / acquire-load on monotonic counter (no L1 flush).
// All cross-CTA h traffic via .cg (L2-only), so no stale-L1 hazard.
// ============================================================================
__global__ void __launch_bounds__(256) lstm_rec(const float* __restrict__ Whh,
                                                int layer, float* __restrict__ dout) {
    __shared__ __align__(16) unsigned sH[16][520];         // packed h tile
    __shared__ float sPart[2][4][16][8];                   // [khalf][gate][batch][unit]

    const int tid = threadIdx.x;
    const int ug = blockIdx.x >> 1, u0 = ug * 8;
    const int bg = blockIdx.x & 1,  b0 = bg * 16;
    const int w = tid >> 5, lane = tid & 31;
    const int g = w >> 1, kh = w & 1, kbase = kh * 256;

    // preload register-resident Whh fragments (split hi/lo)
    unsigned Bwhi[16][2], Bwlo[16][2];
    {
        const float* wr = Whh + (size_t)(g * 512 + u0 + (lane >> 2)) * HH + kbase;
#pragma unroll
        for (int ks = 0; ks < 16; ks++) {
            const int k = ks * 16 + (lane & 3) * 2;
            unsigned short h0, l0, h1, l1;
            split_bf16(wr[k], h0, l0);     split_bf16(wr[k + 1], h1, l1);
            Bwhi[ks][0] = (unsigned)h0 | ((unsigned)h1 << 16);
            Bwlo[ks][0] = (unsigned)l0 | ((unsigned)l1 << 16);
            split_bf16(wr[k + 8], h0, l0); split_bf16(wr[k + 9], h1, l1);
            Bwhi[ks][1] = (unsigned)h0 | ((unsigned)h1 << 16);
            Bwlo[ks][1] = (unsigned)l0 | ((unsigned)l1 << 16);
        }
    }

    float cst = 0.f;
    const int bl = tid >> 3, ul = tid & 7;

    // prefetch gx for t=0 (streaming; independent of recurrence)
    float pgi = 0.f, pgf = 0.f, pgg = 0.f, pgo = 0.f;
    if (tid < 128) {
        const float* gp = g_gx + (size_t)(b0 + bl) * G4 + u0 + ul;
        pgi = __ldcs(gp); pgf = __ldcs(gp + 512);
        pgg = __ldcs(gp + 1024); pgo = __ldcs(gp + 1536);
    }

    for (int t = 0; t < SB; t++) {
        // ---- stage packed h_{t-1} tile into SMEM (L2-only loads) ----
        const uint4* src = nullptr;
        if (t > 0)
            src = (layer == 0)
                ? reinterpret_cast<const uint4*>(g_hseq + ((size_t)(t - 1) * BB + b0) * HH)
                : reinterpret_cast<const uint4*>(g_h1 + b0 * HH);
#pragma unroll
        for (int j = 0; j < 8; j++) {
            const int i4 = tid + j * 256;
            uint4 v = src ? __ldcg(src + i4) : make_uint4(0, 0, 0, 0);
            const int idx = i4 * 4, r = idx >> 9, c = idx & 511;
            *reinterpret_cast<uint4*>(&sH[r][c]) = v;
        }
        __syncthreads();

        // ---- recurrent MMA, 3 independent accumulator chains ----
        float Ca[4] = {0, 0, 0, 0}, Cb[4] = {0, 0, 0, 0}, Cc[4] = {0, 0, 0, 0};
        const int r = lane >> 2;
#pragma unroll
        for (int ks = 0; ks < 16; ks++) {
            const int kk = kbase + ks * 16 + (lane & 3) * 2;
            uint2 p0 = *reinterpret_cast<const uint2*>(&sH[r][kk]);
            uint2 p1 = *reinterpret_cast<const uint2*>(&sH[r + 8][kk]);
            uint2 p2 = *reinterpret_cast<const uint2*>(&sH[r][kk + 8]);
            uint2 p3 = *reinterpret_cast<const uint2*>(&sH[r + 8][kk + 8]);
            unsigned ah[4], al[4];
            ah[0] = __byte_perm(p0.x, p0.y, 0x7632); al[0] = __byte_perm(p0.x, p0.y, 0x5410);
            ah[1] = __byte_perm(p1.x, p1.y, 0x7632); al[1] = __byte_perm(p1.x, p1.y, 0x5410);
            ah[2] = __byte_perm(p2.x, p2.y, 0x7632); al[2] = __byte_perm(p2.x, p2.y, 0x5410);
            ah[3] = __byte_perm(p3.x, p3.y, 0x7632); al[3] = __byte_perm(p3.x, p3.y, 0x5410);
            mma16816(Ca, ah, Bwhi[ks]);
            mma16816(Cb, ah, Bwlo[ks]);
            mma16816(Cc, al, Bwhi[ks]);
        }

        // ---- both K-halves publish partials; elementwise threads sum ----
        {
            const int rr = lane >> 2, cc = (lane & 3) * 2;
            sPart[kh][g][rr][cc]     = Ca[0] + Cb[0] + Cc[0];
            sPart[kh][g][rr][cc + 1] = Ca[1] + Cb[1] + Cc[1];
            sPart[kh][g][rr + 8][cc]     = Ca[2] + Cb[2] + Cc[2];
            sPart[kh][g][rr + 8][cc + 1] = Ca[3] + Cb[3] + Cc[3];
        }
        __syncthreads();

        // ---- LSTM elementwise ----
        if (tid < 128) {
            const float iv = sPart[0][0][bl][ul] + sPart[1][0][bl][ul] + pgi;
            const float fv = sPart[0][1][bl][ul] + sPart[1][1][bl][ul] + pgf;
            const float gv = sPart[0][2][bl][ul] + sPart[1][2][bl][ul] + pgg;
            const float ov = sPart[0][3][bl][ul] + sPart[1][3][bl][ul] + pgo;
            cst = sigf(fv) * cst + sigf(iv) * tanhf(gv);
            const float h = sigf(ov) * tanhf(cst);
            unsigned short hh, hl; split_bf16(h, hh, hl);
            const unsigned hp = ((unsigned)hh << 16) | (unsigned)hl;
            if (layer == 0) {
                __stcg(&g_hseq[((size_t)t * BB + b0 + bl) * HH + u0 + ul], hp);
            } else {
                __stcg(&g_h1[(b0 + bl) * HH + u0 + ul], hp);
                __stcs(&dout[((size_t)(b0 + bl) * SB + t) * HH + u0 + ul], h);
            }
            // prefetch next step's gx while waiting at the barrier
            if (t + 1 < SB) {
                const float* gp = g_gx + ((size_t)(t + 1) * BB + b0 + bl) * G4 + u0 + ul;
                pgi = __ldcs(gp); pgf = __ldcs(gp + 512);
                pgg = __ldcs(gp + 1024); pgo = __ldcs(gp + 1536);
            }
        }
        __syncthreads();

        // ---- grid barrier: release-red + acquire-load spin (no L1 flush) ----
        if (tid == 0) {
            asm volatile("red.release.gpu.add.u32 [%0], 1;" :: "l"(&g_bar) : "memory");
            const unsigned tgt = 128u * (unsigned)(t + 1);
            unsigned v;
            do {
                asm volatile("ld.acquire.gpu.u32 %0, [%1];" : "=r"(v) : "l"(&g_bar) : "memory");
            } while (v < tgt);
        }
        __syncthreads();
    }
}

extern "C" void kernel_launch(void* const* d_in, const int* in_sizes, int n_in,
                              void* d_out, int out_size) {
    const float* X   = (const float*)d_in[0];
    const float* Wih = (const float*)d_in[1];
    const float* Whh = (const float*)d_in[2];
    const float* bih = (const float*)d_in[3];
    const float* bhh = (const float*)d_in[4];
    float* out = (float*)d_out;

    dim3 gg(32, 512);
    gx_gemm<1><<<gg, 256>>>(X, Wih, bih, bhh);
    zero_bar<<<1, 1>>>();
    lstm_rec<<<128, 256>>>(Whh, 0, nullptr);
    gx_gemm<0><<<gg, 256>>>(nullptr, Wih + (size_t)G4 * DD, bih + G4, bhh + G4);
    zero_bar<<<1, 1>>>();
    lstm_rec<<<128, 256>>>(Whh + (size_t)G4 * HH, 1, out);
}

// round 5
// speedup vs baseline: 1.1220x; 1.1211x over previous
#include <cuda_runtime.h>
#include <cuda_bf16.h>

#define SB 2048
#define BB 32
#define DD 512
#define HH 512
#define G4 2048
#define MTOT (SB*BB)

// ---- device scratch (static __device__ globals; no allocations) ----
__device__ float    g_gx[(size_t)MTOT * G4];    // input projections for current layer
__device__ unsigned g_hseq[(size_t)MTOT * HH];  // layer-0 h sequence, packed (hi16|lo16)
__device__ unsigned g_h1[2][BB * HH];           // layer-1 h, DOUBLE-BUFFERED (WAR-safe)
__device__ unsigned g_leaf[8 * 128];            // hierarchical barrier leaves (512B apart)
__device__ unsigned g_epoch;                    // barrier epoch broadcast word

static __device__ __forceinline__ void split_bf16(float v, unsigned short& hi, unsigned short& lo) {
    __nv_bfloat16 h = __float2bfloat16_rn(v);
    float r = v - __bfloat162float(h);
    hi = __bfloat16_as_ushort(h);
    lo = __bfloat16_as_ushort(__float2bfloat16_rn(r));
}

static __device__ __forceinline__ void mma16816(float* d, const unsigned* a, const unsigned* b) {
    asm volatile(
        "mma.sync.aligned.m16n8k16.row.col.f32.bf16.bf16.f32 "
        "{%0,%1,%2,%3}, {%4,%5,%6,%7}, {%8,%9}, {%0,%1,%2,%3};\n"
        : "+f"(d[0]), "+f"(d[1]), "+f"(d[2]), "+f"(d[3])
        : "r"(a[0]), "r"(a[1]), "r"(a[2]), "r"(a[3]), "r"(b[0]), "r"(b[1]));
}

static __device__ __forceinline__ float sigf(float x) { return 1.0f / (1.0f + expf(-x)); }

// ============================================================================
// gx[m][n] = A[m][:].W[n][:] + bias[n];  m = s*32+b.  SRCX=1: A=X fp32, else A=g_hseq packed.
// ============================================================================
template <int SRCX>
__global__ void __launch_bounds__(256) gx_gemm(const float* __restrict__ Xf,
                                               const float* __restrict__ W,
                                               const float* __restrict__ bia,
                                               const float* __restrict__ bib) {
    __shared__ __align__(16) unsigned short sAhi[128][36], sAlo[128][36];
    __shared__ __align__(16) unsigned short sBhi[64][36],  sBlo[64][36];
    __shared__ float sBias[64];

    const int tid = threadIdx.x;
    const int n0 = blockIdx.x * 64, m0 = blockIdx.y * 128;
    if (tid < 64) sBias[tid] = bia[n0 + tid] + bib[n0 + tid];

    const int w = tid >> 5, lane = tid & 31;
    const int wm = w >> 1, wn = w & 1;

    float C[2][4][4];
#pragma unroll
    for (int i = 0; i < 2; i++)
#pragma unroll
        for (int j = 0; j < 4; j++)
#pragma unroll
            for (int k = 0; k < 4; k++) C[i][j][k] = 0.f;

    const int rg = tid >> 3, kq = (tid & 7) * 4;

    for (int kc = 0; kc < 16; kc++) {
        const int k0 = kc * 32;
#pragma unroll
        for (int rr = 0; rr < 4; rr++) {
            const int r = rg + rr * 32, m = m0 + r;
            if (SRCX) {
                const int b = m & 31, s = m >> 5;
                const float4 f = *reinterpret_cast<const float4*>(Xf + ((size_t)(b * SB + s)) * DD + k0 + kq);
                const float v[4] = {f.x, f.y, f.z, f.w};
#pragma unroll
                for (int j = 0; j < 4; j++) {
                    unsigned short hi, lo; split_bf16(v[j], hi, lo);
                    sAhi[r][kq + j] = hi; sAlo[r][kq + j] = lo;
                }
            } else {
                const uint4 u = *reinterpret_cast<const uint4*>(g_hseq + (size_t)m * HH + k0 + kq);
                const unsigned uu[4] = {u.x, u.y, u.z, u.w};
#pragma unroll
                for (int j = 0; j < 4; j++) {
                    sAhi[r][kq + j] = (unsigned short)(uu[j] >> 16);
                    sAlo[r][kq + j] = (unsigned short)(uu[j] & 0xffffu);
                }
            }
        }
#pragma unroll
        for (int rr = 0; rr < 2; rr++) {
            const int r = rg + rr * 32;
            const float4 f = *reinterpret_cast<const float4*>(W + (size_t)(n0 + r) * DD + k0 + kq);
            const float v[4] = {f.x, f.y, f.z, f.w};
#pragma unroll
            for (int j = 0; j < 4; j++) {
                unsigned short hi, lo; split_bf16(v[j], hi, lo);
                sBhi[r][kq + j] = hi; sBlo[r][kq + j] = lo;
            }
        }
        __syncthreads();

#pragma unroll
        for (int ks = 0; ks < 2; ks++) {
            const int kk = ks * 16 + (lane & 3) * 2;
            unsigned Ah[2][4], Al[2][4], Bh[4][2], Bl[4][2];
#pragma unroll
            for (int mt = 0; mt < 2; mt++) {
                const int r = wm * 32 + mt * 16 + (lane >> 2);
                Ah[mt][0] = *(const unsigned*)&sAhi[r][kk];
                Ah[mt][1] = *(const unsigned*)&sAhi[r + 8][kk];
                Ah[mt][2] = *(const unsigned*)&sAhi[r][kk + 8];
                Ah[mt][3] = *(const unsigned*)&sAhi[r + 8][kk + 8];
                Al[mt][0] = *(const unsigned*)&sAlo[r][kk];
                Al[mt][1] = *(const unsigned*)&sAlo[r + 8][kk];
                Al[mt][2] = *(const unsigned*)&sAlo[r][kk + 8];
                Al[mt][3] = *(const unsigned*)&sAlo[r + 8][kk + 8];
            }
#pragma unroll
            for (int nt = 0; nt < 4; nt++) {
                const int n = wn * 32 + nt * 8 + (lane >> 2);
                Bh[nt][0] = *(const unsigned*)&sBhi[n][kk];
                Bh[nt][1] = *(const unsigned*)&sBhi[n][kk + 8];
                Bl[nt][0] = *(const unsigned*)&sBlo[n][kk];
                Bl[nt][1] = *(const unsigned*)&sBlo[n][kk + 8];
            }
#pragma unroll
            for (int mt = 0; mt < 2; mt++)
#pragma unroll
                for (int nt = 0; nt < 4; nt++) {
                    mma16816(C[mt][nt], Ah[mt], Bh[nt]);
                    mma16816(C[mt][nt], Ah[mt], Bl[nt]);
                    mma16816(C[mt][nt], Al[mt], Bh[nt]);
                }
        }
        __syncthreads();
    }

#pragma unroll
    for (int mt = 0; mt < 2; mt++)
#pragma unroll
        for (int nt = 0; nt < 4; nt++) {
            const int r  = m0 + wm * 32 + mt * 16 + (lane >> 2);
            const int cn = wn * 32 + nt * 8 + (lane & 3) * 2;
            const float b0v = sBias[cn], b1v = sBias[cn + 1];
            *reinterpret_cast<float2*>(g_gx + (size_t)r * G4 + n0 + cn) =
                make_float2(C[mt][nt][0] + b0v, C[mt][nt][1] + b1v);
            *reinterpret_cast<float2*>(g_gx + (size_t)(r + 8) * G4 + n0 + cn) =
                make_float2(C[mt][nt][2] + b0v, C[mt][nt][3] + b1v);
        }
}

__global__ void zero_bar() {
    const int i = threadIdx.x;
    if (i < 8) g_leaf[i * 128] = 0;
    if (i == 0) g_epoch = 0;
}

// ============================================================================
// Persistent recurrence: 128 CTAs (64 unit-groups x 2 batch-halves), 256 thr.
// Hierarchical grid barrier: red.release -> 8 leaves (512B apart), CTA0 polls
// with STRONG relaxed loads + acq_rel fence, release-stores epoch; consumers
// ld.acquire on epoch. Layer-1 h double-buffered (WAR-safe).
// ============================================================================
__global__ void __launch_bounds__(256) lstm_rec(const float* __restrict__ Whh,
                                                int layer, float* __restrict__ dout) {
    __shared__ __align__(16) unsigned sH[16][520];         // packed h tile
    __shared__ float sPart[2][4][16][8];                   // [khalf][gate][batch][unit]

    const int tid = threadIdx.x;
    const int ug = blockIdx.x >> 1, u0 = ug * 8;
    const int bg = blockIdx.x & 1,  b0 = bg * 16;
    const int w = tid >> 5, lane = tid & 31;
    const int g = w >> 1, kh = w & 1, kbase = kh * 256;

    // preload register-resident Whh fragments (split hi/lo)
    unsigned Bwhi[16][2], Bwlo[16][2];
    {
        const float* wr = Whh + (size_t)(g * 512 + u0 + (lane >> 2)) * HH + kbase;
#pragma unroll
        for (int ks = 0; ks < 16; ks++) {
            const int k = ks * 16 + (lane & 3) * 2;
            unsigned short h0, l0, h1, l1;
            split_bf16(wr[k], h0, l0);     split_bf16(wr[k + 1], h1, l1);
            Bwhi[ks][0] = (unsigned)h0 | ((unsigned)h1 << 16);
            Bwlo[ks][0] = (unsigned)l0 | ((unsigned)l1 << 16);
            split_bf16(wr[k + 8], h0, l0); split_bf16(wr[k + 9], h1, l1);
            Bwhi[ks][1] = (unsigned)h0 | ((unsigned)h1 << 16);
            Bwlo[ks][1] = (unsigned)l0 | ((unsigned)l1 << 16);
        }
    }

    float cst = 0.f;
    const int bl = tid >> 3, ul = tid & 7;

    // prefetch gx for t=0
    float pgi = 0.f, pgf = 0.f, pgg = 0.f, pgo = 0.f;
    if (tid < 128) {
        const float* gp = g_gx + (size_t)(b0 + bl) * G4 + u0 + ul;
        pgi = __ldcs(gp); pgf = __ldcs(gp + 512);
        pgg = __ldcs(gp + 1024); pgo = __ldcs(gp + 1536);
    }

    for (int t = 0; t < SB; t++) {
        // ---- stage packed h_{t-1} tile into SMEM (L2-only loads) ----
        const uint4* src = nullptr;
        if (t > 0)
            src = (layer == 0)
                ? reinterpret_cast<const uint4*>(g_hseq + ((size_t)(t - 1) * BB + b0) * HH)
                : reinterpret_cast<const uint4*>(g_h1[(t + 1) & 1] + b0 * HH);
#pragma unroll
        for (int j = 0; j < 8; j++) {
            const int i4 = tid + j * 256;
            uint4 v = src ? __ldcg(src + i4) : make_uint4(0, 0, 0, 0);
            const int idx = i4 * 4, r = idx >> 9, c = idx & 511;
            *reinterpret_cast<uint4*>(&sH[r][c]) = v;
        }
        __syncthreads();

        // ---- recurrent MMA, 3 independent accumulator chains ----
        float Ca[4] = {0, 0, 0, 0}, Cb[4] = {0, 0, 0, 0}, Cc[4] = {0, 0, 0, 0};
        const int r = lane >> 2;
#pragma unroll
        for (int ks = 0; ks < 16; ks++) {
            const int kk = kbase + ks * 16 + (lane & 3) * 2;
            uint2 p0 = *reinterpret_cast<const uint2*>(&sH[r][kk]);
            uint2 p1 = *reinterpret_cast<const uint2*>(&sH[r + 8][kk]);
            uint2 p2 = *reinterpret_cast<const uint2*>(&sH[r][kk + 8]);
            uint2 p3 = *reinterpret_cast<const uint2*>(&sH[r + 8][kk + 8]);
            unsigned ah[4], al[4];
            ah[0] = __byte_perm(p0.x, p0.y, 0x7632); al[0] = __byte_perm(p0.x, p0.y, 0x5410);
            ah[1] = __byte_perm(p1.x, p1.y, 0x7632); al[1] = __byte_perm(p1.x, p1.y, 0x5410);
            ah[2] = __byte_perm(p2.x, p2.y, 0x7632); al[2] = __byte_perm(p2.x, p2.y, 0x5410);
            ah[3] = __byte_perm(p3.x, p3.y, 0x7632); al[3] = __byte_perm(p3.x, p3.y, 0x5410);
            mma16816(Ca, ah, Bwhi[ks]);
            mma16816(Cb, ah, Bwlo[ks]);
            mma16816(Cc, al, Bwhi[ks]);
        }

        // ---- both K-halves publish partials; elementwise threads sum ----
        {
            const int rr = lane >> 2, cc = (lane & 3) * 2;
            sPart[kh][g][rr][cc]     = Ca[0] + Cb[0] + Cc[0];
            sPart[kh][g][rr][cc + 1] = Ca[1] + Cb[1] + Cc[1];
            sPart[kh][g][rr + 8][cc]     = Ca[2] + Cb[2] + Cc[2];
            sPart[kh][g][rr + 8][cc + 1] = Ca[3] + Cb[3] + Cc[3];
        }
        __syncthreads();

        // ---- LSTM elementwise ----
        if (tid < 128) {
            const float iv = sPart[0][0][bl][ul] + sPart[1][0][bl][ul] + pgi;
            const float fv = sPart[0][1][bl][ul] + sPart[1][1][bl][ul] + pgf;
            const float gv = sPart[0][2][bl][ul] + sPart[1][2][bl][ul] + pgg;
            const float ov = sPart[0][3][bl][ul] + sPart[1][3][bl][ul] + pgo;
            cst = sigf(fv) * cst + sigf(iv) * tanhf(gv);
            const float h = sigf(ov) * tanhf(cst);
            unsigned short hh, hl; split_bf16(h, hh, hl);
            const unsigned hp = ((unsigned)hh << 16) | (unsigned)hl;
            if (layer == 0) {
                __stcg(&g_hseq[((size_t)t * BB + b0 + bl) * HH + u0 + ul], hp);
            } else {
                __stcg(&g_h1[t & 1][(b0 + bl) * HH + u0 + ul], hp);
                __stcs(&dout[((size_t)(b0 + bl) * SB + t) * HH + u0 + ul], h);
            }
            if (t + 1 < SB) {
                const float* gp = g_gx + ((size_t)(t + 1) * BB + b0 + bl) * G4 + u0 + ul;
                pgi = __ldcs(gp); pgf = __ldcs(gp + 512);
                pgg = __ldcs(gp + 1024); pgo = __ldcs(gp + 1536);
            }
        }
        __syncthreads();

        // ---- hierarchical grid barrier (morally-strong chain) ----
        if (tid == 0) {
            const unsigned tgt = (unsigned)(t + 1);
            asm volatile("red.release.gpu.global.add.u32 [%0], 1;"
                         :: "l"(&g_leaf[(blockIdx.x & 7) * 128]) : "memory");
            if (blockIdx.x == 0) {
                const unsigned leaftgt = 16u * tgt;
                bool done = false;
                while (!done) {
                    unsigned v0, v1, v2, v3, v4, v5, v6, v7;
                    asm volatile("ld.relaxed.gpu.global.u32 %0, [%1];" : "=r"(v0) : "l"(&g_leaf[0 * 128]) : "memory");
                    asm volatile("ld.relaxed.gpu.global.u32 %0, [%1];" : "=r"(v1) : "l"(&g_leaf[1 * 128]) : "memory");
                    asm volatile("ld.relaxed.gpu.global.u32 %0, [%1];" : "=r"(v2) : "l"(&g_leaf[2 * 128]) : "memory");
                    asm volatile("ld.relaxed.gpu.global.u32 %0, [%1];" : "=r"(v3) : "l"(&g_leaf[3 * 128]) : "memory");
                    asm volatile("ld.relaxed.gpu.global.u32 %0, [%1];" : "=r"(v4) : "l"(&g_leaf[4 * 128]) : "memory");
                    asm volatile("ld.relaxed.gpu.global.u32 %0, [%1];" : "=r"(v5) : "l"(&g_leaf[5 * 128]) : "memory");
                    asm volatile("ld.relaxed.gpu.global.u32 %0, [%1];" : "=r"(v6) : "l"(&g_leaf[6 * 128]) : "memory");
                    asm volatile("ld.relaxed.gpu.global.u32 %0, [%1];" : "=r"(v7) : "l"(&g_leaf[7 * 128]) : "memory");
                    done = (v0 >= leaftgt) & (v1 >= leaftgt) & (v2 >= leaftgt) & (v3 >= leaftgt)
                         & (v4 >= leaftgt) & (v5 >= leaftgt) & (v6 >= leaftgt) & (v7 >= leaftgt);
                }
                asm volatile("fence.acq_rel.gpu;" ::: "memory");
                asm volatile("st.release.gpu.global.u32 [%0], %1;" :: "l"(&g_epoch), "r"(tgt) : "memory");
            }
            // acquire spin on the epoch broadcast word (proven round-3 pattern)
            unsigned e;
            do {
                asm volatile("ld.acquire.gpu.global.u32 %0, [%1];" : "=r"(e) : "l"(&g_epoch) : "memory");
            } while (e < tgt);
        }
        __syncthreads();
    }
}

extern "C" void kernel_launch(void* const* d_in, const int* in_sizes, int n_in,
                              void* d_out, int out_size) {
    const float* X   = (const float*)d_in[0];
    const float* Wih = (const float*)d_in[1];
    const float* Whh = (const float*)d_in[2];
    const float* bih = (const float*)d_in[3];
    const float* bhh = (const float*)d_in[4];
    float* out = (float*)d_out;

    dim3 gg(32, 512);
    gx_gemm<1><<<gg, 256>>>(X, Wih, bih, bhh);
    zero_bar<<<1, 32>>>();
    lstm_rec<<<128, 256>>>(Whh, 0, nullptr);
    gx_gemm<0><<<gg, 256>>>(nullptr, Wih + (size_t)G4 * DD, bih + G4, bhh + G4);
    zero_bar<<<1, 32>>>();
    lstm_rec<<<128, 256>>>(Whh + (size_t)G4 * HH, 1, out);
}

// round 6
// speedup vs baseline: 1.2748x; 1.1362x over previous
#include <cuda_runtime.h>
#include <cuda_bf16.h>

#define SB 2048
#define BB 32
#define DD 512
#define HH 512
#define G4 2048
#define MTOT (SB*BB)

// ---- device scratch (static __device__ globals; no allocations) ----
__device__ float    g_gx[(size_t)MTOT * G4];   // layer-0 input projections
__device__ unsigned g_h0[2][BB * HH];          // layer-0 h, double-buffered, packed hi16|lo16
__device__ unsigned g_h1[2][BB * HH];          // layer-1 h, double-buffered, packed
__device__ unsigned g_leaf[8 * 128];           // barrier leaves, 512B apart

static __device__ __forceinline__ void split_bf16(float v, unsigned short& hi, unsigned short& lo) {
    __nv_bfloat16 h = __float2bfloat16_rn(v);
    float r = v - __bfloat162float(h);
    hi = __bfloat16_as_ushort(h);
    lo = __bfloat16_as_ushort(__float2bfloat16_rn(r));
}

static __device__ __forceinline__ void mma16816(float* d, const unsigned* a, const unsigned* b) {
    asm volatile(
        "mma.sync.aligned.m16n8k16.row.col.f32.bf16.bf16.f32 "
        "{%0,%1,%2,%3}, {%4,%5,%6,%7}, {%8,%9}, {%0,%1,%2,%3};\n"
        : "+f"(d[0]), "+f"(d[1]), "+f"(d[2]), "+f"(d[3])
        : "r"(a[0]), "r"(a[1]), "r"(a[2]), "r"(a[3]), "r"(b[0]), "r"(b[1]));
}

static __device__ __forceinline__ float sigf(float x) { return 1.0f / (1.0f + expf(-x)); }

// ============================================================================
// Layer-0 input projection GEMM: gx[m][n] = X_row(m).Wih0[n] + bias, m = s*32+b
// ============================================================================
__global__ void __launch_bounds__(256) gx_gemm(const float* __restrict__ Xf,
                                               const float* __restrict__ W,
                                               const float* __restrict__ bia,
                                               const float* __restrict__ bib) {
    __shared__ __align__(16) unsigned short sAhi[128][36], sAlo[128][36];
    __shared__ __align__(16) unsigned short sBhi[64][36],  sBlo[64][36];
    __shared__ float sBias[64];

    const int tid = threadIdx.x;
    const int n0 = blockIdx.x * 64, m0 = blockIdx.y * 128;
    if (tid < 64) sBias[tid] = bia[n0 + tid] + bib[n0 + tid];

    const int w = tid >> 5, lane = tid & 31;
    const int wm = w >> 1, wn = w & 1;

    float C[2][4][4];
#pragma unroll
    for (int i = 0; i < 2; i++)
#pragma unroll
        for (int j = 0; j < 4; j++)
#pragma unroll
            for (int k = 0; k < 4; k++) C[i][j][k] = 0.f;

    const int rg = tid >> 3, kq = (tid & 7) * 4;

    for (int kc = 0; kc < 16; kc++) {
        const int k0 = kc * 32;
#pragma unroll
        for (int rr = 0; rr < 4; rr++) {
            const int r = rg + rr * 32, m = m0 + r;
            const int b = m & 31, s = m >> 5;
            const float4 f = *reinterpret_cast<const float4*>(Xf + ((size_t)(b * SB + s)) * DD + k0 + kq);
            const float v[4] = {f.x, f.y, f.z, f.w};
#pragma unroll
            for (int j = 0; j < 4; j++) {
                unsigned short hi, lo; split_bf16(v[j], hi, lo);
                sAhi[r][kq + j] = hi; sAlo[r][kq + j] = lo;
            }
        }
#pragma unroll
        for (int rr = 0; rr < 2; rr++) {
            const int r = rg + rr * 32;
            const float4 f = *reinterpret_cast<const float4*>(W + (size_t)(n0 + r) * DD + k0 + kq);
            const float v[4] = {f.x, f.y, f.z, f.w};
#pragma unroll
            for (int j = 0; j < 4; j++) {
                unsigned short hi, lo; split_bf16(v[j], hi, lo);
                sBhi[r][kq + j] = hi; sBlo[r][kq + j] = lo;
            }
        }
        __syncthreads();

#pragma unroll
        for (int ks = 0; ks < 2; ks++) {
            const int kk = ks * 16 + (lane & 3) * 2;
            unsigned Ah[2][4], Al[2][4], Bh[4][2], Bl[4][2];
#pragma unroll
            for (int mt = 0; mt < 2; mt++) {
                const int r = wm * 32 + mt * 16 + (lane >> 2);
                Ah[mt][0] = *(const unsigned*)&sAhi[r][kk];
                Ah[mt][1] = *(const unsigned*)&sAhi[r + 8][kk];
                Ah[mt][2] = *(const unsigned*)&sAhi[r][kk + 8];
                Ah[mt][3] = *(const unsigned*)&sAhi[r + 8][kk + 8];
                Al[mt][0] = *(const unsigned*)&sAlo[r][kk];
                Al[mt][1] = *(const unsigned*)&sAlo[r + 8][kk];
                Al[mt][2] = *(const unsigned*)&sAlo[r][kk + 8];
                Al[mt][3] = *(const unsigned*)&sAlo[r + 8][kk + 8];
            }
#pragma unroll
            for (int nt = 0; nt < 4; nt++) {
                const int n = wn * 32 + nt * 8 + (lane >> 2);
                Bh[nt][0] = *(const unsigned*)&sBhi[n][kk];
                Bh[nt][1] = *(const unsigned*)&sBhi[n][kk + 8];
                Bl[nt][0] = *(const unsigned*)&sBlo[n][kk];
                Bl[nt][1] = *(const unsigned*)&sBlo[n][kk + 8];
            }
#pragma unroll
            for (int mt = 0; mt < 2; mt++)
#pragma unroll
                for (int nt = 0; nt < 4; nt++) {
                    mma16816(C[mt][nt], Ah[mt], Bh[nt]);
                    mma16816(C[mt][nt], Ah[mt], Bl[nt]);
                    mma16816(C[mt][nt], Al[mt], Bh[nt]);
                }
        }
        __syncthreads();
    }

#pragma unroll
    for (int mt = 0; mt < 2; mt++)
#pragma unroll
        for (int nt = 0; nt < 4; nt++) {
            const int r  = m0 + wm * 32 + mt * 16 + (lane >> 2);
            const int cn = wn * 32 + nt * 8 + (lane & 3) * 2;
            const float b0v = sBias[cn], b1v = sBias[cn + 1];
            *reinterpret_cast<float2*>(g_gx + (size_t)r * G4 + n0 + cn) =
                make_float2(C[mt][nt][0] + b0v, C[mt][nt][1] + b1v);
            *reinterpret_cast<float2*>(g_gx + (size_t)(r + 8) * G4 + n0 + cn) =
                make_float2(C[mt][nt][2] + b0v, C[mt][nt][3] + b1v);
        }
}

__global__ void zero_bar() {
    if (threadIdx.x < 8) g_leaf[threadIdx.x * 128] = 0;
}

// ============================================================================
// Fused 2-layer pipelined recurrence.
// 128 CTAs: blocks 0-63 = layer 0 (t = rnd), blocks 64-127 = layer 1 (t = rnd-1).
// CTA = 8 hidden units x ALL 32 batches (two m16 tiles). 8 warps = 4 gates x 2
// K-halves. Layer-1 K-half 0 contracts h0_t with Wih1, half 1 contracts
// h1_{t-1} with Whh1 (fused input projection, no gx GEMM for layer 1).
// ============================================================================
template <int LAY>
static __device__ __forceinline__ void run_layer(
    const float* __restrict__ Wr0,   // LAY0: Whh0 ; LAY1: Wih1
    const float* __restrict__ Wr1,   // LAY1: Whh1
    const float* __restrict__ bi, const float* __restrict__ bh,
    float* __restrict__ dout, unsigned* sH, float* sP)
{
    const int tid = threadIdx.x;
    const int ug = blockIdx.x & 63, u0 = ug * 8;
    const int w = tid >> 5, lane = tid & 31;
    const int g = w >> 1, kh = w & 1;
    constexpr int NKS = LAY ? 32 : 16;      // K-slices of 16 per warp
    constexpr int RS  = LAY ? 1036 : 524;   // sH row stride (bank-safe: %32==12)

    // ---- preload register-resident split-bf16 weight fragments ----
    unsigned Bhi[NKS][2], Blo[NKS][2];
    {
        const int row = g * 512 + u0 + (lane >> 2);
        const float* wr;
        if (LAY == 0) wr = Wr0 + (size_t)row * HH + kh * 256;
        else          wr = (kh ? Wr1 : Wr0) + (size_t)row * HH;
#pragma unroll
        for (int ks = 0; ks < NKS; ks++) {
            const int k = ks * 16 + (lane & 3) * 2;
            unsigned short h0, l0, h1, l1;
            split_bf16(wr[k], h0, l0);     split_bf16(wr[k + 1], h1, l1);
            Bhi[ks][0] = (unsigned)h0 | ((unsigned)h1 << 16);
            Blo[ks][0] = (unsigned)l0 | ((unsigned)l1 << 16);
            split_bf16(wr[k + 8], h0, l0); split_bf16(wr[k + 9], h1, l1);
            Bhi[ks][1] = (unsigned)h0 | ((unsigned)h1 << 16);
            Blo[ks][1] = (unsigned)l0 | ((unsigned)l1 << 16);
        }
    }

    float cst = 0.f;
    const int bl = tid >> 3, ul = tid & 7;   // (batch, unit) for elementwise

    float pg[4];
    if (LAY == 0) {   // prefetch gx for t=0
        const float* gp = g_gx + (size_t)bl * G4 + u0 + ul;
        pg[0] = __ldcs(gp);        pg[1] = __ldcs(gp + 512);
        pg[2] = __ldcs(gp + 1024); pg[3] = __ldcs(gp + 1536);
    } else {          // constant bias
        pg[0] = bi[u0 + ul]        + bh[u0 + ul];
        pg[1] = bi[512 + u0 + ul]  + bh[512 + u0 + ul];
        pg[2] = bi[1024 + u0 + ul] + bh[1024 + u0 + ul];
        pg[3] = bi[1536 + u0 + ul] + bh[1536 + u0 + ul];
    }

    for (int rnd = 0; rnd <= SB; rnd++) {
        const bool act = LAY ? (rnd >= 1) : (rnd < SB);
        const int t = LAY ? (rnd - 1) : rnd;

        // ---- stage packed h into SMEM ----
        if (act) {
            if (LAY == 0) {
                const uint4* src = (t > 0) ? (const uint4*)g_h0[(t + 1) & 1] : nullptr;
#pragma unroll
                for (int j = 0; j < 16; j++) {
                    const int i4 = tid + j * 256;
                    uint4 v = src ? __ldcg(src + i4) : make_uint4(0, 0, 0, 0);
                    const int row = i4 >> 7, c4 = i4 & 127;
                    *reinterpret_cast<uint4*>(&sH[row * RS + c4 * 4]) = v;
                }
            } else {
                const uint4* srcA = (const uint4*)g_h0[t & 1];
                const uint4* srcB = (t > 0) ? (const uint4*)g_h1[(t + 1) & 1] : nullptr;
#pragma unroll
                for (int j = 0; j < 16; j++) {
                    const int i4 = tid + j * 256;
                    const int row = i4 >> 7, c4 = i4 & 127;
                    uint4 va = __ldcg(srcA + i4);
                    *reinterpret_cast<uint4*>(&sH[row * RS + c4 * 4]) = va;
                    uint4 vb = srcB ? __ldcg(srcB + i4) : make_uint4(0, 0, 0, 0);
                    *reinterpret_cast<uint4*>(&sH[row * RS + 512 + c4 * 4]) = vb;
                }
            }
        }
        __syncthreads();

        // ---- MMA: 3-pass split-bf16, fp32 accum ----
        if (act) {
            float Ca[2][4] = {}, Cb[2][4] = {}, Cc[2][4] = {};
            const int r0 = lane >> 2;
            const int kcol0 = (LAY ? kh * 512 : kh * 256) + (lane & 3) * 2;
#pragma unroll
            for (int ks = 0; ks < NKS; ks++) {
                const int kk = kcol0 + ks * 16;
#pragma unroll
                for (int mt = 0; mt < 2; mt++) {
                    const int m = mt * 16 + r0;
                    uint2 p0 = *(const uint2*)&sH[m * RS + kk];
                    uint2 p1 = *(const uint2*)&sH[(m + 8) * RS + kk];
                    uint2 p2 = *(const uint2*)&sH[m * RS + kk + 8];
                    uint2 p3 = *(const uint2*)&sH[(m + 8) * RS + kk + 8];
                    unsigned ah[4], al[4];
                    ah[0] = __byte_perm(p0.x, p0.y, 0x7632); al[0] = __byte_perm(p0.x, p0.y, 0x5410);
                    ah[1] = __byte_perm(p1.x, p1.y, 0x7632); al[1] = __byte_perm(p1.x, p1.y, 0x5410);
                    ah[2] = __byte_perm(p2.x, p2.y, 0x7632); al[2] = __byte_perm(p2.x, p2.y, 0x5410);
                    ah[3] = __byte_perm(p3.x, p3.y, 0x7632); al[3] = __byte_perm(p3.x, p3.y, 0x5410);
                    mma16816(Ca[mt], ah, Bhi[ks]);
                    mma16816(Cb[mt], ah, Blo[ks]);
                    mma16816(Cc[mt], al, Bhi[ks]);
                }
            }
            const int cc = (lane & 3) * 2;
            float* base = sP + (size_t)(kh * 4 + g) * 32 * 8;
#pragma unroll
            for (int mt = 0; mt < 2; mt++) {
                const int rr = mt * 16 + r0;
                base[rr * 8 + cc]           = Ca[mt][0] + Cb[mt][0] + Cc[mt][0];
                base[rr * 8 + cc + 1]       = Ca[mt][1] + Cb[mt][1] + Cc[mt][1];
                base[(rr + 8) * 8 + cc]     = Ca[mt][2] + Cb[mt][2] + Cc[mt][2];
                base[(rr + 8) * 8 + cc + 1] = Ca[mt][3] + Cb[mt][3] + Cc[mt][3];
            }
        }
        __syncthreads();

        // ---- LSTM elementwise: all 256 threads own one (batch, unit) ----
        if (act) {
            const float iv = sP[(size_t)(0 * 4 + 0) * 256 + bl * 8 + ul] + sP[(size_t)(1 * 4 + 0) * 256 + bl * 8 + ul] + pg[0];
            const float fv = sP[(size_t)(0 * 4 + 1) * 256 + bl * 8 + ul] + sP[(size_t)(1 * 4 + 1) * 256 + bl * 8 + ul] + pg[1];
            const float gv = sP[(size_t)(0 * 4 + 2) * 256 + bl * 8 + ul] + sP[(size_t)(1 * 4 + 2) * 256 + bl * 8 + ul] + pg[2];
            const float ov = sP[(size_t)(0 * 4 + 3) * 256 + bl * 8 + ul] + sP[(size_t)(1 * 4 + 3) * 256 + bl * 8 + ul] + pg[3];
            cst = sigf(fv) * cst + sigf(iv) * tanhf(gv);
            const float h = sigf(ov) * tanhf(cst);
            unsigned short hh, hl; split_bf16(h, hh, hl);
            const unsigned hp = ((unsigned)hh << 16) | (unsigned)hl;
            if (LAY == 0) {
                __stcg(&g_h0[t & 1][bl * HH + u0 + ul], hp);
                if (t + 1 < SB) {   // prefetch next gx during barrier wait
                    const float* gp = g_gx + ((size_t)(t + 1) * BB + bl) * G4 + u0 + ul;
                    pg[0] = __ldcs(gp);        pg[1] = __ldcs(gp + 512);
                    pg[2] = __ldcs(gp + 1024); pg[3] = __ldcs(gp + 1536);
                }
            } else {
                __stcg(&g_h1[t & 1][bl * HH + u0 + ul], hp);
                __stcs(&dout[((size_t)bl * SB + t) * HH + u0 + ul], h);
            }
        }
        __syncthreads();

        if (rnd == SB) break;

        // ---- grid barrier: 8 spread leaves, every CTA polls all 8 ----
        if (tid == 0) {
            const unsigned tgt = 16u * (unsigned)(rnd + 1);
            asm volatile("red.release.gpu.global.add.u32 [%0], 1;"
                         :: "l"(&g_leaf[(blockIdx.x & 7) * 128]) : "memory");
            bool done = false;
            while (!done) {
                unsigned v0, v1, v2, v3, v4, v5, v6, v7;
                asm volatile("ld.relaxed.gpu.global.u32 %0, [%1];" : "=r"(v0) : "l"(&g_leaf[0 * 128]) : "memory");
                asm volatile("ld.relaxed.gpu.global.u32 %0, [%1];" : "=r"(v1) : "l"(&g_leaf[1 * 128]) : "memory");
                asm volatile("ld.relaxed.gpu.global.u32 %0, [%1];" : "=r"(v2) : "l"(&g_leaf[2 * 128]) : "memory");
                asm volatile("ld.relaxed.gpu.global.u32 %0, [%1];" : "=r"(v3) : "l"(&g_leaf[3 * 128]) : "memory");
                asm volatile("ld.relaxed.gpu.global.u32 %0, [%1];" : "=r"(v4) : "l"(&g_leaf[4 * 128]) : "memory");
                asm volatile("ld.relaxed.gpu.global.u32 %0, [%1];" : "=r"(v5) : "l"(&g_leaf[5 * 128]) : "memory");
                asm volatile("ld.relaxed.gpu.global.u32 %0, [%1];" : "=r"(v6) : "l"(&g_leaf[6 * 128]) : "memory");
                asm volatile("ld.relaxed.gpu.global.u32 %0, [%1];" : "=r"(v7) : "l"(&g_leaf[7 * 128]) : "memory");
                done = (v0 >= tgt) & (v1 >= tgt) & (v2 >= tgt) & (v3 >= tgt)
                     & (v4 >= tgt) & (v5 >= tgt) & (v6 >= tgt) & (v7 >= tgt);
            }
            asm volatile("fence.acq_rel.gpu;" ::: "memory");
        }
        __syncthreads();
    }
}

__global__ void __launch_bounds__(256, 1) lstm_fused(
    const float* __restrict__ Whh0, const float* __restrict__ Wih1,
    const float* __restrict__ Whh1,
    const float* __restrict__ bi1,  const float* __restrict__ bh1,
    float* __restrict__ dout)
{
    extern __shared__ unsigned smem[];
    unsigned* sH = smem;
    float* sP = (float*)(smem + 32 * 1036);
    if (blockIdx.x < 64) run_layer<0>(Whh0, Whh0, Whh0, Whh0, dout, sH, sP);
    else                 run_layer<1>(Wih1, Whh1, bi1, bh1, dout, sH, sP);
}

extern "C" void kernel_launch(void* const* d_in, const int* in_sizes, int n_in,
                              void* d_out, int out_size) {
    const float* X   = (const float*)d_in[0];
    const float* Wih = (const float*)d_in[1];
    const float* Whh = (const float*)d_in[2];
    const float* bih = (const float*)d_in[3];
    const float* bhh = (const float*)d_in[4];
    float* out = (float*)d_out;

    const int smem_bytes = (32 * 1036 + 2 * 4 * 32 * 8) * 4;  // 140,800 B
    cudaFuncSetAttribute(lstm_fused, cudaFuncAttributeMaxDynamicSharedMemorySize, smem_bytes);

    dim3 gg(32, 512);
    gx_gemm<<<gg, 256>>>(X, Wih, bih, bhh);        // layer-0 input projections
    zero_bar<<<1, 32>>>();
    lstm_fused<<<128, 256, smem_bytes>>>(Whh,                      // Whh0
                                         Wih + (size_t)G4 * DD,    // Wih1
                                         Whh + (size_t)G4 * HH,    // Whh1
                                         bih + G4, bhh + G4, out);
}

// round 8
// speedup vs baseline: 1.7761x; 1.3932x over previous
#include <cuda_runtime.h>
#include <cuda_bf16.h>

#define SB 2048
#define BB 32
#define DD 512
#define HH 512
#define G4 2048
#define MTOT (SB*BB)

// ---- device scratch (static __device__ globals; no allocations) ----
__device__ float    g_gx[(size_t)MTOT * G4];   // layer-0 input projections
__device__ unsigned g_h0[2][BB * HH];          // layer-0 h, double-buffered, packed hi16|lo16
__device__ unsigned g_h1[2][BB * HH];          // layer-1 h, double-buffered, packed
__device__ unsigned g_leaf[8 * 128];           // barrier leaves, 512B apart

static __device__ __forceinline__ void split_bf16(float v, unsigned short& hi, unsigned short& lo) {
    __nv_bfloat16 h = __float2bfloat16_rn(v);
    float r = v - __bfloat162float(h);
    hi = __bfloat16_as_ushort(h);
    lo = __bfloat16_as_ushort(__float2bfloat16_rn(r));
}

static __device__ __forceinline__ void mma16816(float* d, const unsigned* a, const unsigned* b) {
    asm volatile(
        "mma.sync.aligned.m16n8k16.row.col.f32.bf16.bf16.f32 "
        "{%0,%1,%2,%3}, {%4,%5,%6,%7}, {%8,%9}, {%0,%1,%2,%3};\n"
        : "+f"(d[0]), "+f"(d[1]), "+f"(d[2]), "+f"(d[3])
        : "r"(a[0]), "r"(a[1]), "r"(a[2]), "r"(a[3]), "r"(b[0]), "r"(b[1]));
}

static __device__ __forceinline__ float sigf(float x) { return 1.0f / (1.0f + expf(-x)); }

// ============================================================================
// Layer-0 input projection GEMM: gx[m][n] = X_row(m).Wih0[n] + bias, m = s*32+b
// ============================================================================
__global__ void __launch_bounds__(256) gx_gemm(const float* __restrict__ Xf,
                                               const float* __restrict__ W,
                                               const float* __restrict__ bia,
                                               const float* __restrict__ bib) {
    __shared__ __align__(16) unsigned short sAhi[128][36], sAlo[128][36];
    __shared__ __align__(16) unsigned short sBhi[64][36],  sBlo[64][36];
    __shared__ float sBias[64];

    const int tid = threadIdx.x;
    const int n0 = blockIdx.x * 64, m0 = blockIdx.y * 128;
    if (tid < 64) sBias[tid] = bia[n0 + tid] + bib[n0 + tid];

    const int w = tid >> 5, lane = tid & 31;
    const int wm = w >> 1, wn = w & 1;

    float C[2][4][4];
#pragma unroll
    for (int i = 0; i < 2; i++)
#pragma unroll
        for (int j = 0; j < 4; j++)
#pragma unroll
            for (int k = 0; k < 4; k++) C[i][j][k] = 0.f;

    const int rg = tid >> 3, kq = (tid & 7) * 4;

    for (int kc = 0; kc < 16; kc++) {
        const int k0 = kc * 32;
#pragma unroll
        for (int rr = 0; rr < 4; rr++) {
            const int r = rg + rr * 32, m = m0 + r;
            const int b = m & 31, s = m >> 5;
            const float4 f = *reinterpret_cast<const float4*>(Xf + ((size_t)(b * SB + s)) * DD + k0 + kq);
            const float v[4] = {f.x, f.y, f.z, f.w};
#pragma unroll
            for (int j = 0; j < 4; j++) {
                unsigned short hi, lo; split_bf16(v[j], hi, lo);
                sAhi[r][kq + j] = hi; sAlo[r][kq + j] = lo;
            }
        }
#pragma unroll
        for (int rr = 0; rr < 2; rr++) {
            const int r = rg + rr * 32;
            const float4 f = *reinterpret_cast<const float4*>(W + (size_t)(n0 + r) * DD + k0 + kq);
            const float v[4] = {f.x, f.y, f.z, f.w};
#pragma unroll
            for (int j = 0; j < 4; j++) {
                unsigned short hi, lo; split_bf16(v[j], hi, lo);
                sBhi[r][kq + j] = hi; sBlo[r][kq + j] = lo;
            }
        }
        __syncthreads();

#pragma unroll
        for (int ks = 0; ks < 2; ks++) {
            const int kk = ks * 16 + (lane & 3) * 2;
            unsigned Ah[2][4], Al[2][4], Bh[4][2], Bl[4][2];
#pragma unroll
            for (int mt = 0; mt < 2; mt++) {
                const int r = wm * 32 + mt * 16 + (lane >> 2);
                Ah[mt][0] = *(const unsigned*)&sAhi[r][kk];
                Ah[mt][1] = *(const unsigned*)&sAhi[r + 8][kk];
                Ah[mt][2] = *(const unsigned*)&sAhi[r][kk + 8];
                Ah[mt][3] = *(const unsigned*)&sAhi[r + 8][kk + 8];
                Al[mt][0] = *(const unsigned*)&sAlo[r][kk];
                Al[mt][1] = *(const unsigned*)&sAlo[r + 8][kk];
                Al[mt][2] = *(const unsigned*)&sAlo[r][kk + 8];
                Al[mt][3] = *(const unsigned*)&sAlo[r + 8][kk + 8];
            }
#pragma unroll
            for (int nt = 0; nt < 4; nt++) {
                const int n = wn * 32 + nt * 8 + (lane >> 2);
                Bh[nt][0] = *(const unsigned*)&sBhi[n][kk];
                Bh[nt][1] = *(const unsigned*)&sBhi[n][kk + 8];
                Bl[nt][0] = *(const unsigned*)&sBlo[n][kk];
                Bl[nt][1] = *(const unsigned*)&sBlo[n][kk + 8];
            }
#pragma unroll
            for (int mt = 0; mt < 2; mt++)
#pragma unroll
                for (int nt = 0; nt < 4; nt++) {
                    mma16816(C[mt][nt], Ah[mt], Bh[nt]);
                    mma16816(C[mt][nt], Ah[mt], Bl[nt]);
                    mma16816(C[mt][nt], Al[mt], Bh[nt]);
                }
        }
        __syncthreads();
    }

#pragma unroll
    for (int mt = 0; mt < 2; mt++)
#pragma unroll
        for (int nt = 0; nt < 4; nt++) {
            const int r  = m0 + wm * 32 + mt * 16 + (lane >> 2);
            const int cn = wn * 32 + nt * 8 + (lane & 3) * 2;
            const float b0v = sBias[cn], b1v = sBias[cn + 1];
            *reinterpret_cast<float2*>(g_gx + (size_t)r * G4 + n0 + cn) =
                make_float2(C[mt][nt][0] + b0v, C[mt][nt][1] + b1v);
            *reinterpret_cast<float2*>(g_gx + (size_t)(r + 8) * G4 + n0 + cn) =
                make_float2(C[mt][nt][2] + b0v, C[mt][nt][3] + b1v);
        }
}

__global__ void zero_bar() {
    if (threadIdx.x < 8) g_leaf[threadIdx.x * 128] = 0;
}

// ============================================================================
// Fused 2-layer pipelined recurrence.
// 128 CTAs: blocks 0-63 = layer 0 (t = rnd), blocks 64-127 = layer 1 (t = rnd-1).
// CTA = 8 hidden units x 32 batches. NEW warp layout: warp = one K-slice
// (K/8 wide), computing ALL 4 gates -> each A-fragment loaded/split ONCE.
// Layer-1 fuses its input projection as K=1024 ([h0_t ; h1_{t-1}]).
// ============================================================================
template <int LAY>
static __device__ __forceinline__ void run_layer(
    const float* __restrict__ Wa,   // LAY0: Whh0 ; LAY1: Wih1
    const float* __restrict__ Wb,   // LAY1: Whh1
    const float* __restrict__ bi, const float* __restrict__ bh,
    float* __restrict__ dout, unsigned* sH, float* sP)
{
    const int tid = threadIdx.x;
    const int ug = blockIdx.x & 63, u0 = ug * 8;
    const int ws = tid >> 5, lane = tid & 31;
    constexpr int KSL = LAY ? 128 : 64;   // k-range per warp
    constexpr int NKS = KSL / 16;         // 8 (L1) or 4 (L0)
    constexpr int RS  = LAY ? 1036 : 524; // sH row stride in words

    // ---- preload register-resident split-bf16 weight fragments (all 4 gates) ----
    unsigned Bhi[NKS][4][2], Blo[NKS][4][2];
#pragma unroll
    for (int gg = 0; gg < 4; gg++) {
        const int row = gg * 512 + u0 + (lane >> 2);
        const float* wr;
        if (LAY == 0) wr = Wa + (size_t)row * HH + ws * KSL;
        else          wr = (ws < 4) ? (Wa + (size_t)row * HH + ws * 128)
                                    : (Wb + (size_t)row * HH + (ws - 4) * 128);
#pragma unroll
        for (int ks = 0; ks < NKS; ks++) {
            const int k = ks * 16 + (lane & 3) * 2;
            unsigned short h0, l0, h1, l1;
            split_bf16(wr[k], h0, l0);     split_bf16(wr[k + 1], h1, l1);
            Bhi[ks][gg][0] = (unsigned)h0 | ((unsigned)h1 << 16);
            Blo[ks][gg][0] = (unsigned)l0 | ((unsigned)l1 << 16);
            split_bf16(wr[k + 8], h0, l0); split_bf16(wr[k + 9], h1, l1);
            Bhi[ks][gg][1] = (unsigned)h0 | ((unsigned)h1 << 16);
            Blo[ks][gg][1] = (unsigned)l0 | ((unsigned)l1 << 16);
        }
    }

    float cst = 0.f;
    const int bl = tid >> 3, ul = tid & 7;   // (batch, unit) for elementwise

    float pg[4];
    if (LAY == 0) {   // prefetch gx for t=0
        const float* gp = g_gx + (size_t)bl * G4 + u0 + ul;
        pg[0] = __ldcs(gp);        pg[1] = __ldcs(gp + 512);
        pg[2] = __ldcs(gp + 1024); pg[3] = __ldcs(gp + 1536);
    } else {          // constant bias
        pg[0] = bi[u0 + ul]        + bh[u0 + ul];
        pg[1] = bi[512 + u0 + ul]  + bh[512 + u0 + ul];
        pg[2] = bi[1024 + u0 + ul] + bh[1024 + u0 + ul];
        pg[3] = bi[1536 + u0 + ul] + bh[1536 + u0 + ul];
    }

    for (int rnd = 0; rnd <= SB; rnd++) {
        const bool act = LAY ? (rnd >= 1) : (rnd < SB);
        const int t = LAY ? (rnd - 1) : rnd;

        // ---- stage packed h into SMEM ----
        if (act) {
            if (LAY == 0) {
                const uint4* src = (t > 0) ? (const uint4*)g_h0[(t + 1) & 1] : nullptr;
#pragma unroll
                for (int j = 0; j < 16; j++) {
                    const int i4 = tid + j * 256;
                    uint4 v = src ? __ldcg(src + i4) : make_uint4(0, 0, 0, 0);
                    const int row = i4 >> 7, c4 = i4 & 127;
                    *reinterpret_cast<uint4*>(&sH[row * RS + c4 * 4]) = v;
                }
            } else {
                const uint4* srcA = (const uint4*)g_h0[t & 1];
                const uint4* srcB = (t > 0) ? (const uint4*)g_h1[(t + 1) & 1] : nullptr;
#pragma unroll
                for (int j = 0; j < 16; j++) {
                    const int i4 = tid + j * 256;
                    const int row = i4 >> 7, c4 = i4 & 127;
                    uint4 va = __ldcg(srcA + i4);
                    *reinterpret_cast<uint4*>(&sH[row * RS + c4 * 4]) = va;
                    uint4 vb = srcB ? __ldcg(srcB + i4) : make_uint4(0, 0, 0, 0);
                    *reinterpret_cast<uint4*>(&sH[row * RS + 512 + c4 * 4]) = vb;
                }
            }
        }
        __syncthreads();

        // ---- MMA: warp owns K-slice, computes all 4 gates; A split once ----
        if (act) {
            float C[2][4][4];
#pragma unroll
            for (int i = 0; i < 2; i++)
#pragma unroll
                for (int j = 0; j < 4; j++)
#pragma unroll
                    for (int k = 0; k < 4; k++) C[i][j][k] = 0.f;

            const int r0 = lane >> 2;
            const int kbase = ws * KSL + (lane & 3) * 2;
#pragma unroll
            for (int ks = 0; ks < NKS; ks++) {
                const int kk = kbase + ks * 16;
                unsigned ah[2][4], al[2][4];
#pragma unroll
                for (int mt = 0; mt < 2; mt++) {
                    const int m = mt * 16 + r0;
                    uint2 p0 = *(const uint2*)&sH[m * RS + kk];
                    uint2 p1 = *(const uint2*)&sH[(m + 8) * RS + kk];
                    uint2 p2 = *(const uint2*)&sH[m * RS + kk + 8];
                    uint2 p3 = *(const uint2*)&sH[(m + 8) * RS + kk + 8];
                    ah[mt][0] = __byte_perm(p0.x, p0.y, 0x7632); al[mt][0] = __byte_perm(p0.x, p0.y, 0x5410);
                    ah[mt][1] = __byte_perm(p1.x, p1.y, 0x7632); al[mt][1] = __byte_perm(p1.x, p1.y, 0x5410);
                    ah[mt][2] = __byte_perm(p2.x, p2.y, 0x7632); al[mt][2] = __byte_perm(p2.x, p2.y, 0x5410);
                    ah[mt][3] = __byte_perm(p3.x, p3.y, 0x7632); al[mt][3] = __byte_perm(p3.x, p3.y, 0x5410);
                }
#pragma unroll
                for (int mt = 0; mt < 2; mt++)
#pragma unroll
                    for (int gg = 0; gg < 4; gg++) {
                        mma16816(C[mt][gg], ah[mt], Bhi[ks][gg]);
                        mma16816(C[mt][gg], ah[mt], Blo[ks][gg]);
                        mma16816(C[mt][gg], al[mt], Bhi[ks][gg]);
                    }
            }
            // publish partials: sP[ws][gate][batch 32][unit 8]
            const int cc = (lane & 3) * 2;
#pragma unroll
            for (int mt = 0; mt < 2; mt++)
#pragma unroll
                for (int gg = 0; gg < 4; gg++) {
                    float* base = sP + (size_t)((ws * 4 + gg) * 32) * 8;
                    const int m = mt * 16 + r0;
                    base[m * 8 + cc]           = C[mt][gg][0];
                    base[m * 8 + cc + 1]       = C[mt][gg][1];
                    base[(m + 8) * 8 + cc]     = C[mt][gg][2];
                    base[(m + 8) * 8 + cc + 1] = C[mt][gg][3];
                }
        }
        __syncthreads();

        // ---- LSTM elementwise: sum 8 K-slice partials per gate ----
        if (act) {
            float gv4[4];
#pragma unroll
            for (int gg = 0; gg < 4; gg++) {
                float s = pg[gg];
#pragma unroll
                for (int wsl = 0; wsl < 8; wsl++)
                    s += sP[(size_t)((wsl * 4 + gg) * 32 + bl) * 8 + ul];
                gv4[gg] = s;
            }
            cst = sigf(gv4[1]) * cst + sigf(gv4[0]) * tanhf(gv4[2]);
            const float h = sigf(gv4[3]) * tanhf(cst);
            unsigned short hh, hl; split_bf16(h, hh, hl);
            const unsigned hp = ((unsigned)hh << 16) | (unsigned)hl;
            if (LAY == 0) {
                __stcg(&g_h0[t & 1][bl * HH + u0 + ul], hp);
                if (t + 1 < SB) {   // prefetch next gx during barrier wait
                    const float* gp = g_gx + ((size_t)(t + 1) * BB + bl) * G4 + u0 + ul;
                    pg[0] = __ldcs(gp);        pg[1] = __ldcs(gp + 512);
                    pg[2] = __ldcs(gp + 1024); pg[3] = __ldcs(gp + 1536);
                }
            } else {
                __stcg(&g_h1[t & 1][bl * HH + u0 + ul], hp);
                __stcs(&dout[((size_t)bl * SB + t) * HH + u0 + ul], h);
            }
        }
        __syncthreads();

        if (rnd == SB) break;

        // ---- grid barrier: 8 spread leaves, every CTA polls all 8 ----
        if (tid == 0) {
            const unsigned tgt = 16u * (unsigned)(rnd + 1);
            asm volatile("red.release.gpu.global.add.u32 [%0], 1;"
                         :: "l"(&g_leaf[(blockIdx.x & 7) * 128]) : "memory");
            bool done = false;
            while (!done) {
                unsigned v0, v1, v2, v3, v4, v5, v6, v7;
                asm volatile("ld.relaxed.gpu.global.u32 %0, [%1];" : "=r"(v0) : "l"(&g_leaf[0 * 128]) : "memory");
                asm volatile("ld.relaxed.gpu.global.u32 %0, [%1];" : "=r"(v1) : "l"(&g_leaf[1 * 128]) : "memory");
                asm volatile("ld.relaxed.gpu.global.u32 %0, [%1];" : "=r"(v2) : "l"(&g_leaf[2 * 128]) : "memory");
                asm volatile("ld.relaxed.gpu.global.u32 %0, [%1];" : "=r"(v3) : "l"(&g_leaf[3 * 128]) : "memory");
                asm volatile("ld.relaxed.gpu.global.u32 %0, [%1];" : "=r"(v4) : "l"(&g_leaf[4 * 128]) : "memory");
                asm volatile("ld.relaxed.gpu.global.u32 %0, [%1];" : "=r"(v5) : "l"(&g_leaf[5 * 128]) : "memory");
                asm volatile("ld.relaxed.gpu.global.u32 %0, [%1];" : "=r"(v6) : "l"(&g_leaf[6 * 128]) : "memory");
                asm volatile("ld.relaxed.gpu.global.u32 %0, [%1];" : "=r"(v7) : "l"(&g_leaf[7 * 128]) : "memory");
                done = (v0 >= tgt) & (v1 >= tgt) & (v2 >= tgt) & (v3 >= tgt)
                     & (v4 >= tgt) & (v5 >= tgt) & (v6 >= tgt) & (v7 >= tgt);
            }
            asm volatile("fence.acq_rel.gpu;" ::: "memory");
        }
        __syncthreads();
    }
}

__global__ void __launch_bounds__(256, 1) lstm_fused(
    const float* __restrict__ Whh0, const float* __restrict__ Wih1,
    const float* __restrict__ Whh1,
    const float* __restrict__ bi1,  const float* __restrict__ bh1,
    float* __restrict__ dout)
{
    extern __shared__ unsigned smem[];
    unsigned* sH = smem;
    float* sP = (float*)(smem + 32 * 1036);
    if (blockIdx.x < 64) run_layer<0>(Whh0, Whh0, Whh0, Whh0, dout, sH, sP);
    else                 run_layer<1>(Wih1, Whh1, bi1, bh1, dout, sH, sP);
}

extern "C" void kernel_launch(void* const* d_in, const int* in_sizes, int n_in,
                              void* d_out, int out_size) {
    const float* X   = (const float*)d_in[0];
    const float* Wih = (const float*)d_in[1];
    const float* Whh = (const float*)d_in[2];
    const float* bih = (const float*)d_in[3];
    const float* bhh = (const float*)d_in[4];
    float* out = (float*)d_out;

    const int smem_bytes = (32 * 1036 + 8 * 4 * 32 * 8) * 4;  // 165,376 B
    cudaFuncSetAttribute(lstm_fused, cudaFuncAttributeMaxDynamicSharedMemorySize, smem_bytes);

    dim3 gg(32, 512);
    gx_gemm<<<gg, 256>>>(X, Wih, bih, bhh);        // layer-0 input projections
    zero_bar<<<1, 32>>>();
    lstm_fused<<<128, 256, smem_bytes>>>(Whh,                      // Whh0
                                         Wih + (size_t)G4 * DD,    // Wih1
                                         Whh + (size_t)G4 * HH,    // Whh1
                                         bih + G4, bhh + G4, out);
}

// round 9
// speedup vs baseline: 1.7788x; 1.0015x over previous
#include <cuda_runtime.h>
#include <cuda_bf16.h>

#define SB 2048
#define BB 32
#define DD 512
#define HH 512
#define G4 2048
#define MTOT (SB*BB)

// ---- device scratch (static __device__ globals; no allocations) ----
__device__ float    g_gx[(size_t)MTOT * G4];   // layer-0 input projections
__device__ unsigned g_h0[2][BB * HH];          // layer-0 h, double-buffered, packed hi16|lo16
__device__ unsigned g_h1[2][BB * HH];          // layer-1 h, double-buffered, packed
__device__ unsigned g_leaf[12 * 128];          // flag leaves: [0-3]=cntL0 [4-7]=cntL1staged [8-11]=cntL1done

static __device__ __forceinline__ void split_bf16(float v, unsigned short& hi, unsigned short& lo) {
    __nv_bfloat16 h = __float2bfloat16_rn(v);
    float r = v - __bfloat162float(h);
    hi = __bfloat16_as_ushort(h);
    lo = __bfloat16_as_ushort(__float2bfloat16_rn(r));
}

static __device__ __forceinline__ void mma16816(float* d, const unsigned* a, const unsigned* b) {
    asm volatile(
        "mma.sync.aligned.m16n8k16.row.col.f32.bf16.bf16.f32 "
        "{%0,%1,%2,%3}, {%4,%5,%6,%7}, {%8,%9}, {%0,%1,%2,%3};\n"
        : "+f"(d[0]), "+f"(d[1]), "+f"(d[2]), "+f"(d[3])
        : "r"(a[0]), "r"(a[1]), "r"(a[2]), "r"(a[3]), "r"(b[0]), "r"(b[1]));
}

static __device__ __forceinline__ float sigf(float x) { return 1.0f / (1.0f + expf(-x)); }

// poll two 4-leaf banks until bank0 >= t0 and bankX >= t1 on every leaf (tid0 only)
static __device__ __forceinline__ void poll_flags(const unsigned* bank0, const unsigned* bankX,
                                                  unsigned t0, unsigned t1) {
    bool done = false;
    while (!done) {
        unsigned a0, a1, a2, a3, b0, b1, b2, b3;
        asm volatile("ld.relaxed.gpu.global.u32 %0, [%1];" : "=r"(a0) : "l"(bank0 + 0 * 128) : "memory");
        asm volatile("ld.relaxed.gpu.global.u32 %0, [%1];" : "=r"(a1) : "l"(bank0 + 1 * 128) : "memory");
        asm volatile("ld.relaxed.gpu.global.u32 %0, [%1];" : "=r"(a2) : "l"(bank0 + 2 * 128) : "memory");
        asm volatile("ld.relaxed.gpu.global.u32 %0, [%1];" : "=r"(a3) : "l"(bank0 + 3 * 128) : "memory");
        asm volatile("ld.relaxed.gpu.global.u32 %0, [%1];" : "=r"(b0) : "l"(bankX + 0 * 128) : "memory");
        asm volatile("ld.relaxed.gpu.global.u32 %0, [%1];" : "=r"(b1) : "l"(bankX + 1 * 128) : "memory");
        asm volatile("ld.relaxed.gpu.global.u32 %0, [%1];" : "=r"(b2) : "l"(bankX + 2 * 128) : "memory");
        asm volatile("ld.relaxed.gpu.global.u32 %0, [%1];" : "=r"(b3) : "l"(bankX + 3 * 128) : "memory");
        done = (a0 >= t0) & (a1 >= t0) & (a2 >= t0) & (a3 >= t0)
             & (b0 >= t1) & (b1 >= t1) & (b2 >= t1) & (b3 >= t1);
    }
    asm volatile("fence.acq_rel.gpu;" ::: "memory");
}

// ============================================================================
// Layer-0 input projection GEMM: gx[m][n] = X_row(m).Wih0[n] + bias, m = s*32+b
// ============================================================================
__global__ void __launch_bounds__(256) gx_gemm(const float* __restrict__ Xf,
                                               const float* __restrict__ W,
                                               const float* __restrict__ bia,
                                               const float* __restrict__ bib) {
    __shared__ __align__(16) unsigned short sAhi[128][36], sAlo[128][36];
    __shared__ __align__(16) unsigned short sBhi[64][36],  sBlo[64][36];
    __shared__ float sBias[64];

    const int tid = threadIdx.x;
    const int n0 = blockIdx.x * 64, m0 = blockIdx.y * 128;
    if (tid < 64) sBias[tid] = bia[n0 + tid] + bib[n0 + tid];

    const int w = tid >> 5, lane = tid & 31;
    const int wm = w >> 1, wn = w & 1;

    float C[2][4][4];
#pragma unroll
    for (int i = 0; i < 2; i++)
#pragma unroll
        for (int j = 0; j < 4; j++)
#pragma unroll
            for (int k = 0; k < 4; k++) C[i][j][k] = 0.f;

    const int rg = tid >> 3, kq = (tid & 7) * 4;

    for (int kc = 0; kc < 16; kc++) {
        const int k0 = kc * 32;
#pragma unroll
        for (int rr = 0; rr < 4; rr++) {
            const int r = rg + rr * 32, m = m0 + r;
            const int b = m & 31, s = m >> 5;
            const float4 f = *reinterpret_cast<const float4*>(Xf + ((size_t)(b * SB + s)) * DD + k0 + kq);
            const float v[4] = {f.x, f.y, f.z, f.w};
#pragma unroll
            for (int j = 0; j < 4; j++) {
                unsigned short hi, lo; split_bf16(v[j], hi, lo);
                sAhi[r][kq + j] = hi; sAlo[r][kq + j] = lo;
            }
        }
#pragma unroll
        for (int rr = 0; rr < 2; rr++) {
            const int r = rg + rr * 32;
            const float4 f = *reinterpret_cast<const float4*>(W + (size_t)(n0 + r) * DD + k0 + kq);
            const float v[4] = {f.x, f.y, f.z, f.w};
#pragma unroll
            for (int j = 0; j < 4; j++) {
                unsigned short hi, lo; split_bf16(v[j], hi, lo);
                sBhi[r][kq + j] = hi; sBlo[r][kq + j] = lo;
            }
        }
        __syncthreads();

#pragma unroll
        for (int ks = 0; ks < 2; ks++) {
            const int kk = ks * 16 + (lane & 3) * 2;
            unsigned Ah[2][4], Al[2][4], Bh[4][2], Bl[4][2];
#pragma unroll
            for (int mt = 0; mt < 2; mt++) {
                const int r = wm * 32 + mt * 16 + (lane >> 2);
                Ah[mt][0] = *(const unsigned*)&sAhi[r][kk];
                Ah[mt][1] = *(const unsigned*)&sAhi[r + 8][kk];
                Ah[mt][2] = *(const unsigned*)&sAhi[r][kk + 8];
                Ah[mt][3] = *(const unsigned*)&sAhi[r + 8][kk + 8];
                Al[mt][0] = *(const unsigned*)&sAlo[r][kk];
                Al[mt][1] = *(const unsigned*)&sAlo[r + 8][kk];
                Al[mt][2] = *(const unsigned*)&sAlo[r][kk + 8];
                Al[mt][3] = *(const unsigned*)&sAlo[r + 8][kk + 8];
            }
#pragma unroll
            for (int nt = 0; nt < 4; nt++) {
                const int n = wn * 32 + nt * 8 + (lane >> 2);
                Bh[nt][0] = *(const unsigned*)&sBhi[n][kk];
                Bh[nt][1] = *(const unsigned*)&sBhi[n][kk + 8];
                Bl[nt][0] = *(const unsigned*)&sBlo[n][kk];
                Bl[nt][1] = *(const unsigned*)&sBlo[n][kk + 8];
            }
#pragma unroll
            for (int mt = 0; mt < 2; mt++)
#pragma unroll
                for (int nt = 0; nt < 4; nt++) {
                    mma16816(C[mt][nt], Ah[mt], Bh[nt]);
                    mma16816(C[mt][nt], Ah[mt], Bl[nt]);
                    mma16816(C[mt][nt], Al[mt], Bh[nt]);
                }
        }
        __syncthreads();
    }

#pragma unroll
    for (int mt = 0; mt < 2; mt++)
#pragma unroll
        for (int nt = 0; nt < 4; nt++) {
            const int r  = m0 + wm * 32 + mt * 16 + (lane >> 2);
            const int cn = wn * 32 + nt * 8 + (lane & 3) * 2;
            const float b0v = sBias[cn], b1v = sBias[cn + 1];
            *reinterpret_cast<float2*>(g_gx + (size_t)r * G4 + n0 + cn) =
                make_float2(C[mt][nt][0] + b0v, C[mt][nt][1] + b1v);
            *reinterpret_cast<float2*>(g_gx + (size_t)(r + 8) * G4 + n0 + cn) =
                make_float2(C[mt][nt][2] + b0v, C[mt][nt][3] + b1v);
        }
}

__global__ void zero_bar() {
    if (threadIdx.x < 12) g_leaf[threadIdx.x * 128] = 0;
}

// ============================================================================
// Fused 2-layer pipelined recurrence with DECOUPLED flag synchronization.
// Blocks 0-63 = layer 0 (round r -> t=r); blocks 64-127 = layer 1 (t=r-1).
// L0 round r waits: cntL0>=16r (h0 RAW) + cntL1staged>=16(r-1) (h0 WAR).
// L1 round r waits: cntL0>=16r (h0 from L0) + cntL1done>=16(r-1) (own chain).
// ============================================================================
template <int LAY>
static __device__ __forceinline__ void run_layer(
    const float* __restrict__ Wa,   // LAY0: Whh0 ; LAY1: Wih1
    const float* __restrict__ Wb,   // LAY1: Whh1
    const float* __restrict__ bi, const float* __restrict__ bh,
    float* __restrict__ dout, unsigned* sH, float* sP)
{
    const int tid = threadIdx.x;
    const int ug = blockIdx.x & 63, u0 = ug * 8;
    const int ws = tid >> 5, lane = tid & 31;
    const int lf = (int)(blockIdx.x & 3);
    constexpr int KSL = LAY ? 128 : 64;   // k-range per warp
    constexpr int NKS = KSL / 16;         // 8 (L1) or 4 (L0)
    constexpr int RS  = LAY ? 1036 : 524; // sH row stride in words

    // ---- preload register-resident split-bf16 weight fragments (all 4 gates) ----
    unsigned Bhi[NKS][4][2], Blo[NKS][4][2];
#pragma unroll
    for (int gg = 0; gg < 4; gg++) {
        const int row = gg * 512 + u0 + (lane >> 2);
        const float* wr;
        if (LAY == 0) wr = Wa + (size_t)row * HH + ws * KSL;
        else          wr = (ws < 4) ? (Wa + (size_t)row * HH + ws * 128)
                                    : (Wb + (size_t)row * HH + (ws - 4) * 128);
#pragma unroll
        for (int ks = 0; ks < NKS; ks++) {
            const int k = ks * 16 + (lane & 3) * 2;
            unsigned short h0, l0, h1, l1;
            split_bf16(wr[k], h0, l0);     split_bf16(wr[k + 1], h1, l1);
            Bhi[ks][gg][0] = (unsigned)h0 | ((unsigned)h1 << 16);
            Blo[ks][gg][0] = (unsigned)l0 | ((unsigned)l1 << 16);
            split_bf16(wr[k + 8], h0, l0); split_bf16(wr[k + 9], h1, l1);
            Bhi[ks][gg][1] = (unsigned)h0 | ((unsigned)h1 << 16);
            Blo[ks][gg][1] = (unsigned)l0 | ((unsigned)l1 << 16);
        }
    }

    float cst = 0.f;
    const int bl = tid >> 3, ul = tid & 7;   // (batch, unit) for elementwise

    float pg[4];
    if (LAY == 0) {   // prefetch gx for t=0
        const float* gp = g_gx + (size_t)bl * G4 + u0 + ul;
        pg[0] = __ldcs(gp);        pg[1] = __ldcs(gp + 512);
        pg[2] = __ldcs(gp + 1024); pg[3] = __ldcs(gp + 1536);
    } else {          // constant bias
        pg[0] = bi[u0 + ul]        + bh[u0 + ul];
        pg[1] = bi[512 + u0 + ul]  + bh[512 + u0 + ul];
        pg[2] = bi[1024 + u0 + ul] + bh[1024 + u0 + ul];
        pg[3] = bi[1536 + u0 + ul] + bh[1536 + u0 + ul];
    }

    // L1 initial wait: L0 must finish round 0 before L1 round 1 stages h0[0]
    if (LAY == 1) {
        if (tid == 0) poll_flags(g_leaf, g_leaf + 8 * 128, 16u, 0u);
        __syncthreads();
    }

    const int rbeg = LAY ? 1 : 0;
    const int rend = LAY ? SB : SB - 1;   // inclusive

    for (int r = rbeg; r <= rend; r++) {
        const int t = LAY ? (r - 1) : r;

        // ---- stage packed h into SMEM ----
        if (LAY == 0) {
            const uint4* src = (t > 0) ? (const uint4*)g_h0[(t + 1) & 1] : nullptr;
#pragma unroll
            for (int j = 0; j < 16; j++) {
                const int i4 = tid + j * 256;
                uint4 v = src ? __ldcg(src + i4) : make_uint4(0, 0, 0, 0);
                const int row = i4 >> 7, c4 = i4 & 127;
                *reinterpret_cast<uint4*>(&sH[row * RS + c4 * 4]) = v;
            }
        } else {
            const uint4* srcA = (const uint4*)g_h0[t & 1];
            const uint4* srcB = (t > 0) ? (const uint4*)g_h1[(t + 1) & 1] : nullptr;
#pragma unroll
            for (int j = 0; j < 16; j++) {
                const int i4 = tid + j * 256;
                const int row = i4 >> 7, c4 = i4 & 127;
                uint4 va = __ldcg(srcA + i4);
                *reinterpret_cast<uint4*>(&sH[row * RS + c4 * 4]) = va;
                uint4 vb = srcB ? __ldcg(srcB + i4) : make_uint4(0, 0, 0, 0);
                *reinterpret_cast<uint4*>(&sH[row * RS + 512 + c4 * 4]) = vb;
            }
        }
        __syncthreads();

        // L1: signal "staged" (done reading h0/h1 buffers) -> unblocks L0's WAR
        if (LAY == 1 && tid == 0)
            asm volatile("red.relaxed.gpu.global.add.u32 [%0], 1;"
                         :: "l"(&g_leaf[(4 + lf) * 128]) : "memory");

        // ---- MMA: warp owns K-slice, computes all 4 gates; A split once ----
        {
            float C[2][4][4];
#pragma unroll
            for (int i = 0; i < 2; i++)
#pragma unroll
                for (int j = 0; j < 4; j++)
#pragma unroll
                    for (int k = 0; k < 4; k++) C[i][j][k] = 0.f;

            const int r0 = lane >> 2;
            const int kbase = ws * KSL + (lane & 3) * 2;
#pragma unroll
            for (int ks = 0; ks < NKS; ks++) {
                const int kk = kbase + ks * 16;
                unsigned ah[2][4], al[2][4];
#pragma unroll
                for (int mt = 0; mt < 2; mt++) {
                    const int m = mt * 16 + r0;
                    uint2 p0 = *(const uint2*)&sH[m * RS + kk];
                    uint2 p1 = *(const uint2*)&sH[(m + 8) * RS + kk];
                    uint2 p2 = *(const uint2*)&sH[m * RS + kk + 8];
                    uint2 p3 = *(const uint2*)&sH[(m + 8) * RS + kk + 8];
                    ah[mt][0] = __byte_perm(p0.x, p0.y, 0x7632); al[mt][0] = __byte_perm(p0.x, p0.y, 0x5410);
                    ah[mt][1] = __byte_perm(p1.x, p1.y, 0x7632); al[mt][1] = __byte_perm(p1.x, p1.y, 0x5410);
                    ah[mt][2] = __byte_perm(p2.x, p2.y, 0x7632); al[mt][2] = __byte_perm(p2.x, p2.y, 0x5410);
                    ah[mt][3] = __byte_perm(p3.x, p3.y, 0x7632); al[mt][3] = __byte_perm(p3.x, p3.y, 0x5410);
                }
#pragma unroll
                for (int mt = 0; mt < 2; mt++)
#pragma unroll
                    for (int gg = 0; gg < 4; gg++) {
                        mma16816(C[mt][gg], ah[mt], Bhi[ks][gg]);
                        mma16816(C[mt][gg], ah[mt], Blo[ks][gg]);
                        mma16816(C[mt][gg], al[mt], Bhi[ks][gg]);
                    }
            }
            const int cc = (lane & 3) * 2;
#pragma unroll
            for (int mt = 0; mt < 2; mt++)
#pragma unroll
                for (int gg = 0; gg < 4; gg++) {
                    float* base = sP + (size_t)((ws * 4 + gg) * 32) * 8;
                    const int m = mt * 16 + r0;
                    base[m * 8 + cc]           = C[mt][gg][0];
                    base[m * 8 + cc + 1]       = C[mt][gg][1];
                    base[(m + 8) * 8 + cc]     = C[mt][gg][2];
                    base[(m + 8) * 8 + cc + 1] = C[mt][gg][3];
                }
        }
        __syncthreads();

        // ---- LSTM elementwise: sum 8 K-slice partials per gate ----
        {
            float gv4[4];
#pragma unroll
            for (int gg = 0; gg < 4; gg++) {
                float s = pg[gg];
#pragma unroll
                for (int wsl = 0; wsl < 8; wsl++)
                    s += sP[(size_t)((wsl * 4 + gg) * 32 + bl) * 8 + ul];
                gv4[gg] = s;
            }
            cst = sigf(gv4[1]) * cst + sigf(gv4[0]) * tanhf(gv4[2]);
            const float h = sigf(gv4[3]) * tanhf(cst);
            unsigned short hh, hl; split_bf16(h, hh, hl);
            const unsigned hp = ((unsigned)hh << 16) | (unsigned)hl;
            if (LAY == 0) {
                __stcg(&g_h0[t & 1][bl * HH + u0 + ul], hp);
                if (t + 1 < SB) {   // prefetch next gx during flag wait
                    const float* gp = g_gx + ((size_t)(t + 1) * BB + bl) * G4 + u0 + ul;
                    pg[0] = __ldcs(gp);        pg[1] = __ldcs(gp + 512);
                    pg[2] = __ldcs(gp + 1024); pg[3] = __ldcs(gp + 1536);
                }
            } else {
                __stcg(&g_h1[t & 1][bl * HH + u0 + ul], hp);
                __stcs(&dout[((size_t)bl * SB + t) * HH + u0 + ul], h);
            }
        }
        __syncthreads();

        // ---- arrive (release own h stores) + wait for next round's deps ----
        if (tid == 0) {
            asm volatile("red.release.gpu.global.add.u32 [%0], 1;"
                         :: "l"(&g_leaf[((LAY ? 8 : 0) + lf) * 128]) : "memory");
            if (r < rend) {
                // next round rho = r+1: need cntL0 >= 16*rho and partner >= 16*(rho-1)
                poll_flags(g_leaf, g_leaf + (LAY ? 8 : 4) * 128,
                           16u * (unsigned)(r + 1), 16u * (unsigned)r);
            }
        }
        __syncthreads();
    }
}

__global__ void __launch_bounds__(256, 1) lstm_fused(
    const float* __restrict__ Whh0, const float* __restrict__ Wih1,
    const float* __restrict__ Whh1,
    const float* __restrict__ bi1,  const float* __restrict__ bh1,
    float* __restrict__ dout)
{
    extern __shared__ unsigned smem[];
    unsigned* sH = smem;
    float* sP = (float*)(smem + 32 * 1036);
    if (blockIdx.x < 64) run_layer<0>(Whh0, Whh0, Whh0, Whh0, dout, sH, sP);
    else                 run_layer<1>(Wih1, Whh1, bi1, bh1, dout, sH, sP);
}

extern "C" void kernel_launch(void* const* d_in, const int* in_sizes, int n_in,
                              void* d_out, int out_size) {
    const float* X   = (const float*)d_in[0];
    const float* Wih = (const float*)d_in[1];
    const float* Whh = (const float*)d_in[2];
    const float* bih = (const float*)d_in[3];
    const float* bhh = (const float*)d_in[4];
    float* out = (float*)d_out;

    const int smem_bytes = (32 * 1036 + 8 * 4 * 32 * 8) * 4;  // 165,376 B
    cudaFuncSetAttribute(lstm_fused, cudaFuncAttributeMaxDynamicSharedMemorySize, smem_bytes);

    dim3 gg(32, 512);
    gx_gemm<<<gg, 256>>>(X, Wih, bih, bhh);        // layer-0 input projections
    zero_bar<<<1, 32>>>();
    lstm_fused<<<128, 256, smem_bytes>>>(Whh,                      // Whh0
                                         Wih + (size_t)G4 * DD,    // Wih1
                                         Whh + (size_t)G4 * HH,    // Whh1
                                         bih + G4, bhh + G4, out);
}